// round 15
// baseline (speedup 1.0000x reference)
#include <cuda_runtime.h>
#include <cuda_bf16.h>
#include <cuda_fp16.h>
#include <math.h>
#include <stdint.h>

// Problem constants
#define Lc 12
#define Bc 2
#define Tc 448
#define Dc 768
#define Hc 12
#define Vc 51865
#define NCc 448
#define CTc 1500
#define HD 64
#define Mrows (Bc*Tc)      // 896
#define DDm (Dc*Dc)
#define D4 (4*Dc)          // 3072
#define D3 (3*Dc)          // 2304
#define XSPL 4
#define XTPS 6

typedef __nv_bfloat16 bf16;

// -------------------- scratch (static device globals) -----------------------
__device__ __half s_Wqkv_h[(long)Lc*Dc*D3], s_Wqkv_l[(long)Lc*Dc*D3];
__device__ __half s_Wo_h[Lc*DDm],  s_Wo_l[Lc*DDm];
__device__ __half s_xWq_h[Lc*DDm], s_xWq_l[Lc*DDm];
__device__ __half s_xWo_h[Lc*DDm], s_xWo_l[Lc*DDm];
__device__ __half s_W1_h[(long)Lc*Dc*D4], s_W1_l[(long)Lc*Dc*D4];
__device__ __half s_W2_h[(long)Lc*Dc*D4], s_W2_l[(long)Lc*Dc*D4];
__device__ __half s_emb_h[(long)Vc*Dc], s_emb_l[(long)Vc*Dc];
__device__ __half s_ckf[(long)Lc*Bc*CTc*Dc];       // cross K single fp16
__device__ __half s_cvf[(long)Lc*Bc*CTc*Dc];       // cross V single fp16
// activations
__device__ float g_x[Mrows*Dc];
__device__ __half a_hf[Mrows*Dc];          // LN out (fp16, GEMM A)
__device__ __half a_atf[Mrows*Dc];         // attn out (fp16, GEMM A)
__device__ __half a_hidf[Mrows*D4];        // MLP hidden (fp16)
__device__ __half a_qf[Mrows*Dc];          // Q single fp16
__device__ __half a_kf[Mrows*Dc];          // K single fp16
__device__ __half a_vf[Mrows*Dc];          // V single fp16
// split-K flash partials
__device__ float p_O[(long)XSPL * Bc*Hc * Tc * HD];
__device__ float p_m[XSPL * Bc*Hc * Tc];
__device__ float p_l[XSPL * Bc*Hc * Tc];

// -------------------- small helpers ----------------------------------------
__device__ __forceinline__ void cpa16(void* dst, const void* src, int bytes) {
    uint32_t d = (uint32_t)__cvta_generic_to_shared(dst);
    asm volatile("cp.async.cg.shared.global [%0], [%1], 16, %2;\n"
                 :: "r"(d), "l"(src), "r"(bytes));
}
__device__ __forceinline__ void cp_commit() { asm volatile("cp.async.commit_group;\n"); }
__device__ __forceinline__ void cp_wait0()  { asm volatile("cp.async.wait_group 0;\n"); }
__device__ __forceinline__ void cp_wait1()  { asm volatile("cp.async.wait_group 1;\n"); }

__device__ __forceinline__ void ldm4(uint32_t* r, const void* p) {
    uint32_t a = (uint32_t)__cvta_generic_to_shared(p);
    asm volatile("ldmatrix.sync.aligned.m8n8.x4.shared.b16 {%0,%1,%2,%3}, [%4];"
                 : "=r"(r[0]), "=r"(r[1]), "=r"(r[2]), "=r"(r[3]) : "r"(a));
}
__device__ __forceinline__ void ldm4t(uint32_t* r, const void* p) {
    uint32_t a = (uint32_t)__cvta_generic_to_shared(p);
    asm volatile("ldmatrix.sync.aligned.m8n8.x4.trans.shared.b16 {%0,%1,%2,%3}, [%4];"
                 : "=r"(r[0]), "=r"(r[1]), "=r"(r[2]), "=r"(r[3]) : "r"(a));
}
__device__ __forceinline__ void mma16816h(float* d, const uint32_t* a, const uint32_t* b) {
    asm volatile("mma.sync.aligned.m16n8k16.row.col.f32.f16.f16.f32 "
                 "{%0,%1,%2,%3}, {%4,%5,%6,%7}, {%8,%9}, {%0,%1,%2,%3};"
                 : "+f"(d[0]), "+f"(d[1]), "+f"(d[2]), "+f"(d[3])
                 : "r"(a[0]), "r"(a[1]), "r"(a[2]), "r"(a[3]), "r"(b[0]), "r"(b[1]));
}
__device__ __forceinline__ uint32_t packh(float x, float y) {
    __half2 h = __floats2half2_rn(x, y);
    return *(uint32_t*)&h;
}

// -------------------- conversions -------------------------------------------
__global__ void split4h_kernel(const float4* __restrict__ src,
                               __half2* __restrict__ h2,
                               __half2* __restrict__ l2, long n4) {
    long i = (long)blockIdx.x * blockDim.x + threadIdx.x;
    if (i >= n4) return;
    float4 v = src[i];
    __half h0 = __float2half(v.x), h1 = __float2half(v.y);
    __half h2v = __float2half(v.z), h3 = __float2half(v.w);
    h2[2*i]   = __half2(h0, h1);
    h2[2*i+1] = __half2(h2v, h3);
    l2[2*i]   = __half2(__float2half(v.x - __half2float(h0)),
                        __float2half(v.y - __half2float(h1)));
    l2[2*i+1] = __half2(__float2half(v.z - __half2float(h2v)),
                        __float2half(v.w - __half2float(h3)));
}

// plain fp32 -> fp16 convert
__global__ void cvt4h_kernel(const float4* __restrict__ src,
                             __half2* __restrict__ dst, long n4) {
    long i = (long)blockIdx.x * blockDim.x + threadIdx.x;
    if (i >= n4) return;
    float4 v = src[i];
    dst[2*i]   = __floats2half2_rn(v.x, v.y);
    dst[2*i+1] = __floats2half2_rn(v.z, v.w);
}

// merged strided fp16 split: Wq,Wk,Wv -> [L][768][2304] hi/lo
__global__ void split_qkv3h_kernel(const float4* __restrict__ sq,
                                   const float4* __restrict__ sk,
                                   const float4* __restrict__ sv,
                                   __half2* __restrict__ h2,
                                   __half2* __restrict__ l2, long n4) {
    long i = (long)blockIdx.x * blockDim.x + threadIdx.x;
    if (i >= n4) return;
    const float4* src = (blockIdx.y == 0) ? sq : (blockIdx.y == 1) ? sk : sv;
    int dstoff4 = blockIdx.y * 192;
    long row = i / 192;
    int c4 = (int)(i - row * 192);
    long d4 = row * 576 + dstoff4 + c4;
    float4 v = src[i];
    __half h0 = __float2half(v.x), h1 = __float2half(v.y);
    __half h2v = __float2half(v.z), h3 = __float2half(v.w);
    h2[2*d4]   = __half2(h0, h1);
    h2[2*d4+1] = __half2(h2v, h3);
    l2[2*d4]   = __half2(__float2half(v.x - __half2float(h0)),
                         __float2half(v.y - __half2float(h1)));
    l2[2*d4+1] = __half2(__float2half(v.z - __half2float(h2v)),
                         __float2half(v.w - __half2float(h3)));
}

// -------------------- reductions --------------------------------------------
__device__ __forceinline__ float blk_sum(float v) {
    __shared__ float s[32];
    int lane = threadIdx.x & 31, warp = threadIdx.x >> 5;
    #pragma unroll
    for (int o = 16; o > 0; o >>= 1) v += __shfl_down_sync(0xffffffffu, v, o);
    if (lane == 0) s[warp] = v;
    __syncthreads();
    int nw = blockDim.x >> 5;
    v = (threadIdx.x < nw) ? s[threadIdx.x] : 0.f;
    if (warp == 0) {
        #pragma unroll
        for (int o = 16; o > 0; o >>= 1) v += __shfl_down_sync(0xffffffffu, v, o);
        if (lane == 0) s[0] = v;
    }
    __syncthreads();
    float r = s[0];
    __syncthreads();
    return r;
}

// -------------------- embed / ln --------------------------------------------
__global__ void embed_kernel(const int* __restrict__ tokens,
                             const float* __restrict__ tokemb,
                             const float* __restrict__ pos,
                             float* __restrict__ x) {
    int row = blockIdx.x;
    int t = row % Tc;
    int tok = tokens[row];
    const float* te = tokemb + (long)tok * Dc;
    const float* pe = pos + (long)t * Dc;
    float* out = x + (long)row * Dc;
    for (int d = threadIdx.x; d < Dc; d += blockDim.x)
        out[d] = te[d] + pe[d];
}

__global__ void ln_half_kernel(const float* __restrict__ x,
                               __half* __restrict__ oh,
                               const float* __restrict__ g, const float* __restrict__ b) {
    const float* row = x + (long)blockIdx.x * Dc;
    long base = (long)blockIdx.x * Dc;
    int tid = threadIdx.x;
    float v0 = row[tid], v1 = row[tid + 256], v2 = row[tid + 512];
    float s  = blk_sum(v0 + v1 + v2);
    float s2 = blk_sum(v0*v0 + v1*v1 + v2*v2);
    float mean = s * (1.f / (float)Dc);
    float var = s2 * (1.f / (float)Dc) - mean * mean;
    float inv = rsqrtf(var + 1e-5f);
    #pragma unroll
    for (int j = 0; j < 3; j++) {
        int d = tid + j * 256;
        float v = (j == 0) ? v0 : (j == 1) ? v1 : v2;
        oh[base + d] = __float2half((v - mean) * inv * g[d] + b[d]);
    }
}

// -------------------- flash (pure fp16 1-term) -------------------------------
template<int CAUSAL>
__global__ __launch_bounds__(128)
void flash_kernel(const __half* __restrict__ Q,
                  const __half* __restrict__ Kf, const __half* __restrict__ Vf,
                  __half* __restrict__ O,
                  int kvlen, int kvrows) {
    constexpr int LDK = HD + 8;
    __shared__ __half sK[64 * LDK];
    __shared__ __half sV[64 * LDK];

    int z = blockIdx.z;
    int b = z / Hc, h = z - b * Hc;
    int qt = blockIdx.y;
    int q0 = qt * 64;
    long qoff = (long)b * Tc * Dc + h * HD;
    long koff = (long)b * kvrows * Dc + h * HD;
    Q += qoff; O += qoff;
    Kf += koff; Vf += koff;

    int tid = threadIdx.x, lane = tid & 31, warp = tid >> 5;

    // stage Q through sK
    #pragma unroll
    for (int i = 0; i < 4; i++) {
        int idx = i * 128 + tid;
        int row = idx >> 3, c = (idx & 7) * 8;
        cpa16(&sK[row * LDK + c], Q + (long)(q0 + row) * Dc + c, 16);
    }
    cp_commit(); cp_wait0();
    __syncthreads();
    uint32_t qf[4][4];
    #pragma unroll
    for (int kc = 0; kc < 4; kc++)
        ldm4(qf[kc], &sK[(warp*16 + (lane & 15)) * LDK + kc*16 + (lane >> 4) * 8]);
    __syncthreads();

    float m0 = -1e30f, m1 = -1e30f, l0 = 0.f, l1 = 0.f;
    float oacc[8][4] = {};

    int ntile = CAUSAL ? (qt + 1) : ((kvlen + 63) >> 6);
    int qrow0 = q0 + warp*16 + (lane >> 2);
    int qrow1 = qrow0 + 8;

    for (int j = 0; j < ntile; j++) {
        int k0 = j * 64;
        #pragma unroll
        for (int i = 0; i < 4; i++) {
            int idx = i * 128 + tid;
            int row = idx >> 3, c = (idx & 7) * 8;
            int inb = (k0 + row < kvlen);
            int bytes = inb ? 16 : 0;
            long off = inb ? ((long)(k0 + row) * Dc + c) : 0;
            cpa16(&sK[row * LDK + c], Kf + off, bytes);
            cpa16(&sV[row * LDK + c], Vf + off, bytes);
        }
        cp_commit(); cp_wait0();
        __syncthreads();

        // S = Q @ K^T (1-term)
        float s[8][4] = {};
        #pragma unroll
        for (int kc = 0; kc < 4; kc++) {
            uint32_t bh[8][2];
            #pragma unroll
            for (int nf2 = 0; nf2 < 4; nf2++) {
                uint32_t r[4];
                ldm4(r, &sK[(nf2*16 + (lane & 15)) * LDK + kc*16 + (lane >> 4) * 8]);
                bh[2*nf2][0] = r[0]; bh[2*nf2+1][0] = r[1];
                bh[2*nf2][1] = r[2]; bh[2*nf2+1][1] = r[3];
            }
            #pragma unroll
            for (int nf = 0; nf < 8; nf++)
                mma16816h(s[nf], qf[kc], bh[nf]);
        }

        // scale + mask
        #pragma unroll
        for (int nf = 0; nf < 8; nf++) {
            #pragma unroll
            for (int e = 0; e < 4; e++) {
                int col = k0 + nf*8 + (lane & 3)*2 + (e & 1);
                int qr = (e < 2) ? qrow0 : qrow1;
                bool ok = (col < kvlen) && (!CAUSAL || col <= qr);
                s[nf][e] = ok ? (s[nf][e] * 0.125f) : -1e30f;
            }
        }

        // online softmax
        float rm0 = -1e30f, rm1 = -1e30f;
        #pragma unroll
        for (int nf = 0; nf < 8; nf++) {
            rm0 = fmaxf(rm0, fmaxf(s[nf][0], s[nf][1]));
            rm1 = fmaxf(rm1, fmaxf(s[nf][2], s[nf][3]));
        }
        rm0 = fmaxf(rm0, __shfl_xor_sync(0xffffffffu, rm0, 1));
        rm0 = fmaxf(rm0, __shfl_xor_sync(0xffffffffu, rm0, 2));
        rm1 = fmaxf(rm1, __shfl_xor_sync(0xffffffffu, rm1, 1));
        rm1 = fmaxf(rm1, __shfl_xor_sync(0xffffffffu, rm1, 2));
        float mn0 = fmaxf(m0, rm0), mn1 = fmaxf(m1, rm1);
        float f0 = __expf(m0 - mn0), f1 = __expf(m1 - mn1);
        float rs0 = 0.f, rs1 = 0.f;
        #pragma unroll
        for (int nf = 0; nf < 8; nf++) {
            float p0 = __expf(s[nf][0] - mn0);
            float p1 = __expf(s[nf][1] - mn0);
            float p2 = __expf(s[nf][2] - mn1);
            float p3 = __expf(s[nf][3] - mn1);
            s[nf][0] = p0; s[nf][1] = p1; s[nf][2] = p2; s[nf][3] = p3;
            rs0 += p0 + p1;
            rs1 += p2 + p3;
        }
        rs0 += __shfl_xor_sync(0xffffffffu, rs0, 1);
        rs0 += __shfl_xor_sync(0xffffffffu, rs0, 2);
        rs1 += __shfl_xor_sync(0xffffffffu, rs1, 1);
        rs1 += __shfl_xor_sync(0xffffffffu, rs1, 2);
        l0 = l0 * f0 + rs0;
        l1 = l1 * f1 + rs1;
        m0 = mn0; m1 = mn1;
        #pragma unroll
        for (int nf = 0; nf < 8; nf++) {
            oacc[nf][0] *= f0; oacc[nf][1] *= f0;
            oacc[nf][2] *= f1; oacc[nf][3] *= f1;
        }

        // P frags (single fp16)
        uint32_t pa[4][4];
        #pragma unroll
        for (int kc = 0; kc < 4; kc++) {
            pa[kc][0] = packh(s[2*kc][0],   s[2*kc][1]);
            pa[kc][1] = packh(s[2*kc][2],   s[2*kc][3]);
            pa[kc][2] = packh(s[2*kc+1][0], s[2*kc+1][1]);
            pa[kc][3] = packh(s[2*kc+1][2], s[2*kc+1][3]);
        }

        // O += P @ V (1-term)
        #pragma unroll
        for (int kk = 0; kk < 4; kk++) {
            uint32_t vfh[8][2];
            #pragma unroll
            for (int nf2 = 0; nf2 < 4; nf2++) {
                uint32_t r[4];
                ldm4t(r, &sV[(kk*16 + (lane & 15)) * LDK + nf2*16 + (lane >> 4) * 8]);
                vfh[2*nf2][0] = r[0]; vfh[2*nf2][1] = r[1];
                vfh[2*nf2+1][0] = r[2]; vfh[2*nf2+1][1] = r[3];
            }
            #pragma unroll
            for (int nf = 0; nf < 8; nf++)
                mma16816h(oacc[nf], pa[kk], vfh[nf]);
        }
        __syncthreads();
    }

    float il0 = 1.f / l0, il1 = 1.f / l1;
    #pragma unroll
    for (int nf = 0; nf < 8; nf++) {
        int col = nf*8 + (lane & 3)*2;
        *(__half2*)&O[(long)qrow0 * Dc + col] =
            __floats2half2_rn(oacc[nf][0] * il0, oacc[nf][1] * il0);
        *(__half2*)&O[(long)qrow1 * Dc + col] =
            __floats2half2_rn(oacc[nf][2] * il1, oacc[nf][3] * il1);
    }
}

// -------------------- split-K flash (pure fp16 1-term, partials) -------------
__global__ __launch_bounds__(128)
void flashp_kernel(const __half* __restrict__ Q,
                   const __half* __restrict__ Kf, const __half* __restrict__ Vf,
                   float* __restrict__ pO, float* __restrict__ pm,
                   float* __restrict__ pl, int kvlen) {
    constexpr int LDK = HD + 8;
    __shared__ __half sK[64 * LDK];
    __shared__ __half sV[64 * LDK];

    int sp = blockIdx.x;
    int z = blockIdx.z;
    int b = z / Hc, h = z - b * Hc;
    int qt = blockIdx.y;
    int q0 = qt * 64;
    long qoff = (long)b * Tc * Dc + h * HD;
    long koff = (long)b * CTc * Dc + h * HD;
    Q += qoff;
    Kf += koff; Vf += koff;

    int tid = threadIdx.x, lane = tid & 31, warp = tid >> 5;

    #pragma unroll
    for (int i = 0; i < 4; i++) {
        int idx = i * 128 + tid;
        int row = idx >> 3, c = (idx & 7) * 8;
        cpa16(&sK[row * LDK + c], Q + (long)(q0 + row) * Dc + c, 16);
    }
    cp_commit(); cp_wait0();
    __syncthreads();
    uint32_t qf[4][4];
    #pragma unroll
    for (int kc = 0; kc < 4; kc++)
        ldm4(qf[kc], &sK[(warp*16 + (lane & 15)) * LDK + kc*16 + (lane >> 4) * 8]);
    __syncthreads();

    float m0 = -1e30f, m1 = -1e30f, l0 = 0.f, l1 = 0.f;
    float oacc[8][4] = {};

    int jlo = sp * XTPS, jhi = jlo + XTPS;
    int qrow0 = q0 + warp*16 + (lane >> 2);
    int qrow1 = qrow0 + 8;

    for (int j = jlo; j < jhi; j++) {
        int k0 = j * 64;
        #pragma unroll
        for (int i = 0; i < 4; i++) {
            int idx = i * 128 + tid;
            int row = idx >> 3, c = (idx & 7) * 8;
            int inb = (k0 + row < kvlen);
            int bytes = inb ? 16 : 0;
            long off = inb ? ((long)(k0 + row) * Dc + c) : 0;
            cpa16(&sK[row * LDK + c], Kf + off, bytes);
            cpa16(&sV[row * LDK + c], Vf + off, bytes);
        }
        cp_commit(); cp_wait0();
        __syncthreads();

        float s[8][4] = {};
        #pragma unroll
        for (int kc = 0; kc < 4; kc++) {
            uint32_t bh[8][2];
            #pragma unroll
            for (int nf2 = 0; nf2 < 4; nf2++) {
                uint32_t r[4];
                ldm4(r, &sK[(nf2*16 + (lane & 15)) * LDK + kc*16 + (lane >> 4) * 8]);
                bh[2*nf2][0] = r[0]; bh[2*nf2+1][0] = r[1];
                bh[2*nf2][1] = r[2]; bh[2*nf2+1][1] = r[3];
            }
            #pragma unroll
            for (int nf = 0; nf < 8; nf++)
                mma16816h(s[nf], qf[kc], bh[nf]);
        }

        #pragma unroll
        for (int nf = 0; nf < 8; nf++) {
            #pragma unroll
            for (int e = 0; e < 4; e++) {
                int col = k0 + nf*8 + (lane & 3)*2 + (e & 1);
                s[nf][e] = (col < kvlen) ? (s[nf][e] * 0.125f) : -1e30f;
            }
        }

        float rm0 = -1e30f, rm1 = -1e30f;
        #pragma unroll
        for (int nf = 0; nf < 8; nf++) {
            rm0 = fmaxf(rm0, fmaxf(s[nf][0], s[nf][1]));
            rm1 = fmaxf(rm1, fmaxf(s[nf][2], s[nf][3]));
        }
        rm0 = fmaxf(rm0, __shfl_xor_sync(0xffffffffu, rm0, 1));
        rm0 = fmaxf(rm0, __shfl_xor_sync(0xffffffffu, rm0, 2));
        rm1 = fmaxf(rm1, __shfl_xor_sync(0xffffffffu, rm1, 1));
        rm1 = fmaxf(rm1, __shfl_xor_sync(0xffffffffu, rm1, 2));
        float mn0 = fmaxf(m0, rm0), mn1 = fmaxf(m1, rm1);
        float f0 = __expf(m0 - mn0), f1 = __expf(m1 - mn1);
        float rs0 = 0.f, rs1 = 0.f;
        #pragma unroll
        for (int nf = 0; nf < 8; nf++) {
            float p0 = __expf(s[nf][0] - mn0);
            float p1 = __expf(s[nf][1] - mn0);
            float p2 = __expf(s[nf][2] - mn1);
            float p3 = __expf(s[nf][3] - mn1);
            s[nf][0] = p0; s[nf][1] = p1; s[nf][2] = p2; s[nf][3] = p3;
            rs0 += p0 + p1;
            rs1 += p2 + p3;
        }
        rs0 += __shfl_xor_sync(0xffffffffu, rs0, 1);
        rs0 += __shfl_xor_sync(0xffffffffu, rs0, 2);
        rs1 += __shfl_xor_sync(0xffffffffu, rs1, 1);
        rs1 += __shfl_xor_sync(0xffffffffu, rs1, 2);
        l0 = l0 * f0 + rs0;
        l1 = l1 * f1 + rs1;
        m0 = mn0; m1 = mn1;
        #pragma unroll
        for (int nf = 0; nf < 8; nf++) {
            oacc[nf][0] *= f0; oacc[nf][1] *= f0;
            oacc[nf][2] *= f1; oacc[nf][3] *= f1;
        }

        uint32_t pa[4][4];
        #pragma unroll
        for (int kc = 0; kc < 4; kc++) {
            pa[kc][0] = packh(s[2*kc][0],   s[2*kc][1]);
            pa[kc][1] = packh(s[2*kc][2],   s[2*kc][3]);
            pa[kc][2] = packh(s[2*kc+1][0], s[2*kc+1][1]);
            pa[kc][3] = packh(s[2*kc+1][2], s[2*kc+1][3]);
        }

        #pragma unroll
        for (int kk = 0; kk < 4; kk++) {
            uint32_t vfh[8][2];
            #pragma unroll
            for (int nf2 = 0; nf2 < 4; nf2++) {
                uint32_t r[4];
                ldm4t(r, &sV[(kk*16 + (lane & 15)) * LDK + nf2*16 + (lane >> 4) * 8]);
                vfh[2*nf2][0] = r[0]; vfh[2*nf2][1] = r[1];
                vfh[2*nf2+1][0] = r[2]; vfh[2*nf2+1][1] = r[3];
            }
            #pragma unroll
            for (int nf = 0; nf < 8; nf++)
                mma16816h(oacc[nf], pa[kk], vfh[nf]);
        }
        __syncthreads();
    }

    long base = ((long)sp * (Bc*Hc) + z) * Tc;
    if ((lane & 3) == 0) {
        pm[base + qrow0] = m0; pl[base + qrow0] = l0;
        pm[base + qrow1] = m1; pl[base + qrow1] = l1;
    }
    #pragma unroll
    for (int nf = 0; nf < 8; nf++) {
        int col = nf*8 + (lane & 3)*2;
        float2* d0 = (float2*)&pO[(base + qrow0) * HD + col];
        float2* d1 = (float2*)&pO[(base + qrow1) * HD + col];
        *d0 = make_float2(oacc[nf][0], oacc[nf][1]);
        *d1 = make_float2(oacc[nf][2], oacc[nf][3]);
    }
}

__global__ void flashc_kernel(const float* __restrict__ pO,
                              const float* __restrict__ pm,
                              const float* __restrict__ pl,
                              __half* __restrict__ O) {
    int row = blockIdx.x, z = blockIdx.y, c = threadIdx.x;
    int b = z / Hc, h = z - b * Hc;
    float ms[XSPL];
    float mstar = -1e30f;
    #pragma unroll
    for (int s = 0; s < XSPL; s++) {
        ms[s] = pm[((long)s * (Bc*Hc) + z) * Tc + row];
        mstar = fmaxf(mstar, ms[s]);
    }
    float osum = 0.f, lsum = 0.f;
    #pragma unroll
    for (int s = 0; s < XSPL; s++) {
        long base = ((long)s * (Bc*Hc) + z) * Tc + row;
        float w = __expf(ms[s] - mstar);
        lsum += w * pl[base];
        osum += w * pO[base * HD + c];
    }
    long oi = (long)b * Tc * Dc + (long)row * Dc + h * HD + c;
    O[oi] = __float2half(osum / lsum);
}

// -------------------- fp16 2-term GEMM (BM=64, TRANSB=0) --------------------
__global__ __launch_bounds__(128)
void gemm_h2(const __half* __restrict__ A,
             const __half* __restrict__ Bh, const __half* __restrict__ Bl,
             float* Cf, __half* Chf,
             const float* __restrict__ bias,
             int M, int N, int K, int lda, int ldb, int ldc, int mode) {
    constexpr int BM = 64, BN = 64, BK = 32;
    constexpr int LDA = BK + 8, LDB = BN + 8;

    __shared__ __half sA[2][BM * LDA];
    __shared__ __half sB[2][2][BK * LDB];

    int tid = threadIdx.x;
    int lane = tid & 31, warp = tid >> 5;
    int wm = warp >> 1, wn = warp & 1;
    int m0 = blockIdx.x * BM, n0 = blockIdx.y * BN;

    auto load_stage = [&](int s, int kt) {
        int k0 = kt * BK;
        #pragma unroll
        for (int i = 0; i < 2; i++) {
            int idx = i * 128 + tid;
            int row = idx >> 2, kc = (idx & 3) * 8;
            cpa16(&sA[s][row * LDA + kc], A + (long)(m0 + row) * lda + k0 + kc, 16);
        }
        #pragma unroll
        for (int i = 0; i < 2; i++) {
            int idx = i * 128 + tid;
            int krow = idx >> 3, nc = (idx & 7) * 8;
            long off = (long)(k0 + krow) * ldb + n0 + nc;
            cpa16(&sB[s][0][krow * LDB + nc], Bh + off, 16);
            cpa16(&sB[s][1][krow * LDB + nc], Bl + off, 16);
        }
    };

    float acc[2][4][4] = {};
    int KT = K / BK;

    load_stage(0, 0);
    cp_commit();

    for (int kt = 0; kt < KT; kt++) {
        int cur = kt & 1;
        bool more = (kt + 1 < KT);
        if (more) { load_stage(cur ^ 1, kt + 1); cp_commit(); }
        if (more) cp_wait1(); else cp_wait0();
        __syncthreads();

        #pragma unroll
        for (int kf = 0; kf < 2; kf++) {
            uint32_t ah[2][4];
            #pragma unroll
            for (int mf = 0; mf < 2; mf++)
                ldm4(ah[mf], &sA[cur][(wm*32 + mf*16 + (lane & 15)) * LDA + kf*16 + (lane >> 4) * 8]);
            uint32_t bh[4][2], bl[4][2];
            #pragma unroll
            for (int nf2 = 0; nf2 < 2; nf2++) {
                uint32_t r[4];
                ldm4t(r, &sB[cur][0][(kf*16 + (lane & 15)) * LDB + wn*32 + nf2*16 + (lane >> 4) * 8]);
                bh[2*nf2][0] = r[0]; bh[2*nf2][1] = r[1];
                bh[2*nf2+1][0] = r[2]; bh[2*nf2+1][1] = r[3];
                ldm4t(r, &sB[cur][1][(kf*16 + (lane & 15)) * LDB + wn*32 + nf2*16 + (lane >> 4) * 8]);
                bl[2*nf2][0] = r[0]; bl[2*nf2][1] = r[1];
                bl[2*nf2+1][0] = r[2]; bl[2*nf2+1][1] = r[3];
            }
            #pragma unroll
            for (int mf = 0; mf < 2; mf++)
                #pragma unroll
                for (int nf = 0; nf < 4; nf++) {
                    mma16816h(acc[mf][nf], ah[mf], bh[nf]);
                    mma16816h(acc[mf][nf], ah[mf], bl[nf]);
                }
        }
        __syncthreads();
    }

    int r = lane >> 2, c = (lane & 3) * 2;
    #pragma unroll
    for (int mf = 0; mf < 2; mf++) {
        #pragma unroll
        for (int i = 0; i < 2; i++) {
            int grow = m0 + wm*32 + mf*16 + r + i*8;
            #pragma unroll
            for (int nf = 0; nf < 4; nf++) {
                #pragma unroll
                for (int j = 0; j < 2; j++) {
                    int gcol = n0 + wn*32 + nf*8 + c + j;
                    float v = acc[mf][nf][i*2 + j];
                    long ci = (long)grow * ldc + gcol;
                    if (mode >= 1) v += bias[gcol];
                    if (mode == 2) v += Cf[ci];
                    if (mode == 3) v = 0.5f * v * (1.f + erff(v * 0.70710678118654752f));
                    if (Cf) Cf[ci] = v;
                    if (Chf) Chf[ci] = __float2half(v);
                }
            }
        }
    }
}

// -------------------- fp16 2-term small-tile GEMM (BM=32) -------------------
__global__ __launch_bounds__(128)
void gemm_h2_sm(const __half* __restrict__ A,
                const __half* __restrict__ Bh, const __half* __restrict__ Bl,
                float* Cf, __half* Chf,
                const float* __restrict__ bias,
                int M, int N, int K, int lda, int ldb, int ldc, int mode) {
    constexpr int BM = 32, BN = 64, BK = 32;
    constexpr int LDA = BK + 8, LDB = BN + 8;

    __shared__ __half sA[2][BM * LDA];
    __shared__ __half sB[2][2][BK * LDB];

    int tid = threadIdx.x;
    int lane = tid & 31, wn = tid >> 5;
    int m0 = blockIdx.x * BM, n0 = blockIdx.y * BN;

    auto load_stage = [&](int s, int kt) {
        int k0 = kt * BK;
        {
            int row = tid >> 2, kc = (tid & 3) * 8;
            cpa16(&sA[s][row * LDA + kc], A + (long)(m0 + row) * lda + k0 + kc, 16);
        }
        #pragma unroll
        for (int i = 0; i < 2; i++) {
            int idx = i * 128 + tid;
            int krow = idx >> 3, nc = (idx & 7) * 8;
            long off = (long)(k0 + krow) * ldb + n0 + nc;
            cpa16(&sB[s][0][krow * LDB + nc], Bh + off, 16);
            cpa16(&sB[s][1][krow * LDB + nc], Bl + off, 16);
        }
    };

    float acc[2][2][4] = {};
    int KT = K / BK;

    load_stage(0, 0);
    cp_commit();

    for (int kt = 0; kt < KT; kt++) {
        int cur = kt & 1;
        bool more = (kt + 1 < KT);
        if (more) { load_stage(cur ^ 1, kt + 1); cp_commit(); }
        if (more) cp_wait1(); else cp_wait0();
        __syncthreads();

        #pragma unroll
        for (int kf = 0; kf < 2; kf++) {
            uint32_t ah[2][4];
            #pragma unroll
            for (int mf = 0; mf < 2; mf++)
                ldm4(ah[mf], &sA[cur][(mf*16 + (lane & 15)) * LDA + kf*16 + (lane >> 4) * 8]);
            uint32_t bh[2][2], bl[2][2];
            {
                uint32_t r[4];
                ldm4t(r, &sB[cur][0][(kf*16 + (lane & 15)) * LDB + wn*16 + (lane >> 4) * 8]);
                bh[0][0] = r[0]; bh[0][1] = r[1];
                bh[1][0] = r[2]; bh[1][1] = r[3];
                ldm4t(r, &sB[cur][1][(kf*16 + (lane & 15)) * LDB + wn*16 + (lane >> 4) * 8]);
                bl[0][0] = r[0]; bl[0][1] = r[1];
                bl[1][0] = r[2]; bl[1][1] = r[3];
            }
            #pragma unroll
            for (int mf = 0; mf < 2; mf++)
                #pragma unroll
                for (int nf = 0; nf < 2; nf++) {
                    mma16816h(acc[mf][nf], ah[mf], bh[nf]);
                    mma16816h(acc[mf][nf], ah[mf], bl[nf]);
                }
        }
        __syncthreads();
    }

    int r = lane >> 2, c = (lane & 3) * 2;
    #pragma unroll
    for (int mf = 0; mf < 2; mf++) {
        #pragma unroll
        for (int i = 0; i < 2; i++) {
            int grow = m0 + mf*16 + r + i*8;
            #pragma unroll
            for (int nf = 0; nf < 2; nf++) {
                #pragma unroll
                for (int j = 0; j < 2; j++) {
                    int gcol = n0 + wn*16 + nf*8 + c + j;
                    float v = acc[mf][nf][i*2 + j];
                    long ci = (long)grow * ldc + gcol;
                    if (mode >= 1) v += bias[gcol];
                    if (mode == 2) v += Cf[ci];
                    if (mode == 3) v = 0.5f * v * (1.f + erff(v * 0.70710678118654752f));
                    if (Cf) Cf[ci] = v;
                    if (Chf) Chf[ci] = __float2half(v);
                }
            }
        }
    }
}

// -------------------- fp16 fused QKV GEMM ------------------------------------
// region 0: q -> single fp16; 1: k -> cache fp32 + single fp16; 2: v likewise + bias
__global__ __launch_bounds__(128)
void gemm_qkv_h2(const __half* __restrict__ A,
                 const __half* __restrict__ Bh, const __half* __restrict__ Bl,
                 const float* __restrict__ bq, const float* __restrict__ bv,
                 __half* __restrict__ qf,
                 __half* __restrict__ kf, __half* __restrict__ vf,
                 float* __restrict__ kcache, float* __restrict__ vcache) {
    constexpr int BM = 64, BN = 64, BK = 32;
    constexpr int LDA = BK + 8, LDB = BN + 8;
    const int K = Dc, ldb = D3, lda = Dc;

    __shared__ __half sA[2][BM * LDA];
    __shared__ __half sB[2][2][BK * LDB];

    int tid = threadIdx.x;
    int lane = tid & 31, warp = tid >> 5;
    int wm = warp >> 1, wn = warp & 1;
    int m0 = blockIdx.x * BM, n0 = blockIdx.y * BN;

    int reg = n0 / Dc;
    int cn0 = n0 - reg * Dc;
    const float* bias = (reg == 0) ? bq : (reg == 2 ? bv : nullptr);
    float* Cf = (reg == 1) ? kcache : (reg == 2 ? vcache : nullptr);
    __half* Ch = (reg == 0) ? qf : (reg == 1 ? kf : vf);

    auto load_stage = [&](int s, int kt) {
        int k0 = kt * BK;
        #pragma unroll
        for (int i = 0; i < 2; i++) {
            int idx = i * 128 + tid;
            int row = idx >> 2, kc = (idx & 3) * 8;
            cpa16(&sA[s][row * LDA + kc], A + (long)(m0 + row) * lda + k0 + kc, 16);
        }
        #pragma unroll
        for (int i = 0; i < 2; i++) {
            int idx = i * 128 + tid;
            int krow = idx >> 3, nc = (idx & 7) * 8;
            long off = (long)(k0 + krow) * ldb + n0 + nc;
            cpa16(&sB[s][0][krow * LDB + nc], Bh + off, 16);
            cpa16(&sB[s][1][krow * LDB + nc], Bl + off, 16);
        }
    };

    float acc[2][4][4] = {};
    int KT = K / BK;

    load_stage(0, 0);
    cp_commit();

    for (int kt = 0; kt < KT; kt++) {
        int cur = kt & 1;
        bool more = (kt + 1 < KT);
        if (more) { load_stage(cur ^ 1, kt + 1); cp_commit(); }
        if (more) cp_wait1(); else cp_wait0();
        __syncthreads();

        #pragma unroll
        for (int kf2 = 0; kf2 < 2; kf2++) {
            uint32_t ah[2][4];
            #pragma unroll
            for (int mf = 0; mf < 2; mf++)
                ldm4(ah[mf], &sA[cur][(wm*32 + mf*16 + (lane & 15)) * LDA + kf2*16 + (lane >> 4) * 8]);
            uint32_t bh[4][2], bl[4][2];
            #pragma unroll
            for (int nf2 = 0; nf2 < 2; nf2++) {
                uint32_t r[4];
                ldm4t(r, &sB[cur][0][(kf2*16 + (lane & 15)) * LDB + wn*32 + nf2*16 + (lane >> 4) * 8]);
                bh[2*nf2][0] = r[0]; bh[2*nf2][1] = r[1];
                bh[2*nf2+1][0] = r[2]; bh[2*nf2+1][1] = r[3];
                ldm4t(r, &sB[cur][1][(kf2*16 + (lane & 15)) * LDB + wn*32 + nf2*16 + (lane >> 4) * 8]);
                bl[2*nf2][0] = r[0]; bl[2*nf2][1] = r[1];
                bl[2*nf2+1][0] = r[2]; bl[2*nf2+1][1] = r[3];
            }
            #pragma unroll
            for (int mf = 0; mf < 2; mf++)
                #pragma unroll
                for (int nf = 0; nf < 4; nf++) {
                    mma16816h(acc[mf][nf], ah[mf], bh[nf]);
                    mma16816h(acc[mf][nf], ah[mf], bl[nf]);
                }
        }
        __syncthreads();
    }

    int r = lane >> 2, c = (lane & 3) * 2;
    #pragma unroll
    for (int mf = 0; mf < 2; mf++) {
        #pragma unroll
        for (int i = 0; i < 2; i++) {
            int grow = m0 + wm*32 + mf*16 + r + i*8;
            #pragma unroll
            for (int nf = 0; nf < 4; nf++) {
                #pragma unroll
                for (int j = 0; j < 2; j++) {
                    int col = cn0 + wn*32 + nf*8 + c + j;
                    float v = acc[mf][nf][i*2 + j];
                    if (bias) v += bias[col];
                    long ci = (long)grow * Dc + col;
                    if (Cf) Cf[ci] = v;
                    Ch[ci] = __float2half(v);
                }
            }
        }
    }
}

// -------------------- fp16 2-term logits GEMM (TRANSB=1) ---------------------
__global__ __launch_bounds__(128)
void gemm_f16_logits(const __half* __restrict__ A,
                     const __half* __restrict__ Bh, const __half* __restrict__ Bl,
                     float* __restrict__ Cf,
                     int M, int N, int K, int lda, int ldb, int ldc) {
    constexpr int BM = 64, BN = 64, BK = 32;
    constexpr int LDA = BK + 8, LDB = BK + 8;

    __shared__ __half sA[2][BM * LDA];
    __shared__ __half sB[2][2][BN * LDB];

    int tid = threadIdx.x;
    int lane = tid & 31, warp = tid >> 5;
    int wm = warp >> 1, wn = warp & 1;
    int m0 = blockIdx.x * BM, n0 = blockIdx.y * BN;

    auto load_stage = [&](int s, int kt) {
        int k0 = kt * BK;
        #pragma unroll
        for (int i = 0; i < 2; i++) {
            int idx = i * 128 + tid;
            int row = idx >> 2, kc = (idx & 3) * 8;
            cpa16(&sA[s][row * LDA + kc], A + (long)(m0 + row) * lda + k0 + kc, 16);
        }
        #pragma unroll
        for (int i = 0; i < 2; i++) {
            int idx = i * 128 + tid;
            int nrow = idx >> 2, kc = (idx & 3) * 8;
            int gn = n0 + nrow;
            int bytes = (gn < N) ? 16 : 0;
            long off = (long)(gn < N ? gn : 0) * ldb + k0 + kc;
            cpa16(&sB[s][0][nrow * LDB + kc], Bh + off, bytes);
            cpa16(&sB[s][1][nrow * LDB + kc], Bl + off, bytes);
        }
    };

    float acc[2][4][4] = {};
    int KT = K / BK;

    load_stage(0, 0);
    cp_commit();

    for (int kt = 0; kt < KT; kt++) {
        int cur = kt & 1;
        bool more = (kt + 1 < KT);
        if (more) { load_stage(cur ^ 1, kt + 1); cp_commit(); }
        if (more) cp_wait1(); else cp_wait0();
        __syncthreads();

        #pragma unroll
        for (int kf = 0; kf < 2; kf++) {
            uint32_t ah[2][4];
            #pragma unroll
            for (int mf = 0; mf < 2; mf++)
                ldm4(ah[mf], &sA[cur][(wm*32 + mf*16 + (lane & 15)) * LDA + kf*16 + (lane >> 4) * 8]);
            uint32_t bh[4][2], bl[4][2];
            #pragma unroll
            for (int nf2 = 0; nf2 < 2; nf2++) {
                uint32_t r[4];
                ldm4(r, &sB[cur][0][(wn*32 + nf2*16 + (lane & 15)) * LDB + kf*16 + (lane >> 4) * 8]);
                bh[2*nf2][0] = r[0]; bh[2*nf2+1][0] = r[1];
                bh[2*nf2][1] = r[2]; bh[2*nf2+1][1] = r[3];
                ldm4(r, &sB[cur][1][(wn*32 + nf2*16 + (lane & 15)) * LDB + kf*16 + (lane >> 4) * 8]);
                bl[2*nf2][0] = r[0]; bl[2*nf2+1][0] = r[1];
                bl[2*nf2][1] = r[2]; bl[2*nf2+1][1] = r[3];
            }
            #pragma unroll
            for (int mf = 0; mf < 2; mf++)
                #pragma unroll
                for (int nf = 0; nf < 4; nf++) {
                    mma16816h(acc[mf][nf], ah[mf], bh[nf]);
                    mma16816h(acc[mf][nf], ah[mf], bl[nf]);
                }
        }
        __syncthreads();
    }

    int r = lane >> 2, c = (lane & 3) * 2;
    #pragma unroll
    for (int mf = 0; mf < 2; mf++) {
        #pragma unroll
        for (int i = 0; i < 2; i++) {
            int grow = m0 + wm*32 + mf*16 + r + i*8;
            #pragma unroll
            for (int nf = 0; nf < 4; nf++) {
                #pragma unroll
                for (int j = 0; j < 2; j++) {
                    int gcol = n0 + wn*32 + nf*8 + c + j;
                    if (gcol >= N) continue;
                    Cf[(long)grow * ldc + gcol] = acc[mf][nf][i*2 + j];
                }
            }
        }
    }
}

// -------------------- host helpers ------------------------------------------
static inline void split_fp16(cudaStream_t st, const float* src, __half* h, __half* l, long n) {
    long n4 = n / 4;
    int blocks = (int)((n4 + 255) / 256);
    split4h_kernel<<<blocks, 256, 0, st>>>((const float4*)src, (__half2*)h,
                                           (__half2*)l, n4);
}
static inline void cvt_fp16(cudaStream_t st, const float* src, __half* dst, long n) {
    long n4 = n / 4;
    int blocks = (int)((n4 + 255) / 256);
    cvt4h_kernel<<<blocks, 256, 0, st>>>((const float4*)src, (__half2*)dst, n4);
}
static inline void gh2(const __half* A, const __half* Bh, const __half* Bl,
                       float* Cf, __half* Chf, const float* bias,
                       int M, int N, int K, int lda, int ldb, int ldc, int mode) {
    dim3 grid(M / 64, N / 64);
    gemm_h2<<<grid, 128>>>(A, Bh, Bl, Cf, Chf, bias, M, N, K, lda, ldb, ldc, mode);
}
static inline void gh2_sm(const __half* A, const __half* Bh, const __half* Bl,
                          float* Cf, __half* Chf, const float* bias,
                          int M, int N, int K, int lda, int ldb, int ldc, int mode) {
    dim3 grid(M / 32, N / 64);
    gemm_h2_sm<<<grid, 128>>>(A, Bh, Bl, Cf, Chf, bias, M, N, K, lda, ldb, ldc, mode);
}

#define SYM(p, s) cudaGetSymbolAddress((void**)&p, s)

extern "C" void kernel_launch(void* const* d_in, const int* in_sizes, int n_in,
                              void* d_out, int out_size) {
    const int*   tokens    = (const int*)  d_in[0];
    const float* cross_k   = (const float*)d_in[3];
    const float* cross_v   = (const float*)d_in[4];
    const float* tokemb    = (const float*)d_in[6];
    const float* posemb    = (const float*)d_in[7];
    const float* attn_ln_g = (const float*)d_in[9];
    const float* attn_ln_b = (const float*)d_in[10];
    const float* Wq_all    = (const float*)d_in[11];
    const float* bq_all    = (const float*)d_in[12];
    const float* Wk_all    = (const float*)d_in[13];
    const float* Wv_all    = (const float*)d_in[14];
    const float* bv_all    = (const float*)d_in[15];
    const float* Wo_all    = (const float*)d_in[16];
    const float* bo_all    = (const float*)d_in[17];
    const float* xln_g     = (const float*)d_in[18];
    const float* xln_b     = (const float*)d_in[19];
    const float* xWq_all   = (const float*)d_in[20];
    const float* xbq_all   = (const float*)d_in[21];
    const float* xWo_all   = (const float*)d_in[22];
    const float* xbo_all   = (const float*)d_in[23];
    const float* mln_g     = (const float*)d_in[24];
    const float* mln_b     = (const float*)d_in[25];
    const float* W1_all    = (const float*)d_in[26];
    const float* b1_all    = (const float*)d_in[27];
    const float* W2_all    = (const float*)d_in[28];
    const float* b2_all    = (const float*)d_in[29];
    const float* ln_g      = (const float*)d_in[30];
    const float* ln_b      = (const float*)d_in[31];

    float* logits = (float*)d_out;
    float* kout = logits + (long)Bc * Tc * Vc;
    float* vout = kout + (long)Lc * Bc * NCc * Dc;

    static cudaStream_t s2 = nullptr;
    static cudaEvent_t evFork, evWo, evXat, evMlp, evEmb;
    if (!s2) {
        cudaStreamCreateWithFlags(&s2, cudaStreamNonBlocking);
        cudaEventCreateWithFlags(&evFork, cudaEventDisableTiming);
        cudaEventCreateWithFlags(&evWo,   cudaEventDisableTiming);
        cudaEventCreateWithFlags(&evXat,  cudaEventDisableTiming);
        cudaEventCreateWithFlags(&evMlp,  cudaEventDisableTiming);
        cudaEventCreateWithFlags(&evEmb,  cudaEventDisableTiming);
    }

    __half *wqkv_h, *wqkv_l, *wo_h, *wo_l, *xwq_h, *xwq_l, *xwo_h, *xwo_l;
    __half *w1_h, *w1_l, *w2_h, *w2_l, *emb_h, *emb_l;
    __half *ckf, *cvf;
    float *gx, *pO, *pm, *pl;
    __half *hf, *atf, *hidf, *qf, *kf, *vf;
    SYM(wqkv_h, s_Wqkv_h); SYM(wqkv_l, s_Wqkv_l);
    SYM(wo_h, s_Wo_h);  SYM(wo_l, s_Wo_l);
    SYM(xwq_h, s_xWq_h); SYM(xwq_l, s_xWq_l);
    SYM(xwo_h, s_xWo_h); SYM(xwo_l, s_xWo_l);
    SYM(w1_h, s_W1_h);  SYM(w1_l, s_W1_l);
    SYM(w2_h, s_W2_h);  SYM(w2_l, s_W2_l);
    SYM(emb_h, s_emb_h); SYM(emb_l, s_emb_l);
    SYM(ckf, s_ckf);  SYM(cvf, s_cvf);
    SYM(gx, g_x);
    SYM(pO, p_O); SYM(pm, p_m); SYM(pl, p_l);
    SYM(hf, a_hf); SYM(atf, a_atf); SYM(hidf, a_hidf);
    SYM(qf, a_qf); SYM(kf, a_kf); SYM(vf, a_vf);

    const long XKV = (long)Bc * CTc * Dc;
    const long LBD = (long)Bc * NCc * Dc;
    const long WQKV = (long)Dc * D3;

    // ---- fork side stream; one-time splits on s2 ----
    cudaEventRecord(evFork, 0);
    cudaStreamWaitEvent(s2, evFork, 0);

    split_fp16(s2, Wo_all,  wo_h,  wo_l,  (long)Lc * DDm);
    cudaEventRecord(evWo, s2);
    split_fp16(s2, xWq_all, xwq_h, xwq_l, (long)Lc * DDm);
    cvt_fp16(s2, cross_k, ckf, (long)Lc * Bc * CTc * Dc);
    cvt_fp16(s2, cross_v, cvf, (long)Lc * Bc * CTc * Dc);
    split_fp16(s2, xWo_all, xwo_h, xwo_l, (long)Lc * DDm);
    cudaEventRecord(evXat, s2);
    split_fp16(s2, W1_all,  w1_h,  w1_l,  (long)Lc * Dc * D4);
    split_fp16(s2, W2_all,  w2_h,  w2_l,  (long)Lc * Dc * D4);
    cudaEventRecord(evMlp, s2);
    split_fp16(s2, tokemb,  emb_h, emb_l, (long)Vc * Dc);
    cudaEventRecord(evEmb, s2);

    // ---- main stream ----
    {
        long n4 = (long)Lc * Dc * 192;
        dim3 grid((unsigned)((n4 + 255) / 256), 3);
        split_qkv3h_kernel<<<grid, 256>>>((const float4*)Wq_all, (const float4*)Wk_all,
                                          (const float4*)Wv_all,
                                          (__half2*)wqkv_h, (__half2*)wqkv_l, n4);
    }
    embed_kernel<<<Mrows, 256>>>(tokens, tokemb, posemb, gx);

    for (int l = 0; l < Lc; l++) {
        float* klayer = kout + l * LBD;
        float* vlayer = vout + l * LBD;

        // ---- self attention ----
        ln_half_kernel<<<Mrows, 256>>>(gx, hf, attn_ln_g + l * Dc, attn_ln_b + l * Dc);
        gemm_qkv_h2<<<dim3(Mrows/64, D3/64), 128>>>(hf,
                                                    wqkv_h + l * WQKV, wqkv_l + l * WQKV,
                                                    bq_all + l * Dc, bv_all + l * Dc,
                                                    qf, kf, vf, klayer, vlayer);
        flash_kernel<1><<<dim3(1, Tc/64, Bc*Hc), 128>>>(qf, kf, vf, atf, Tc, Tc);
        if (l == 0) cudaStreamWaitEvent(0, evWo, 0);
        gh2_sm(atf, wo_h + (long)l*DDm, wo_l + (long)l*DDm, gx, nullptr,
               bo_all + l*Dc, Mrows, Dc, Dc, Dc, Dc, Dc, 2);

        // ---- cross attention (split-K flash) ----
        ln_half_kernel<<<Mrows, 256>>>(gx, hf, xln_g + l * Dc, xln_b + l * Dc);
        if (l == 0) cudaStreamWaitEvent(0, evXat, 0);
        gh2_sm(hf, xwq_h + (long)l*DDm, xwq_l + (long)l*DDm, nullptr, qf,
               xbq_all + l*Dc, Mrows, Dc, Dc, Dc, Dc, Dc, 1);
        flashp_kernel<<<dim3(XSPL, Tc/64, Bc*Hc), 128>>>(qf,
                                                         ckf + l*XKV, cvf + l*XKV,
                                                         pO, pm, pl, CTc);
        flashc_kernel<<<dim3(Tc, Bc*Hc), HD>>>(pO, pm, pl, atf);
        gh2_sm(atf, xwo_h + (long)l*DDm, xwo_l + (long)l*DDm, gx, nullptr,
               xbo_all + l*Dc, Mrows, Dc, Dc, Dc, Dc, Dc, 2);

        // ---- MLP ----
        ln_half_kernel<<<Mrows, 256>>>(gx, hf, mln_g + l * Dc, mln_b + l * Dc);
        if (l == 0) cudaStreamWaitEvent(0, evMlp, 0);
        gh2(hf, w1_h + (long)l*Dc*D4, w1_l + (long)l*Dc*D4, nullptr, hidf,
            b1_all + (long)l*D4, Mrows, D4, Dc, Dc, D4, D4, 3);
        gh2_sm(hidf, w2_h + (long)l*Dc*D4, w2_l + (long)l*Dc*D4, gx, nullptr,
               b2_all + l*Dc, Mrows, Dc, D4, D4, Dc, Dc, 2);
    }

    // final LN (fp16) + fp16 2-term logits GEMM
    ln_half_kernel<<<Mrows, 256>>>(gx, hf, ln_g, ln_b);
    cudaStreamWaitEvent(0, evEmb, 0);
    {
        dim3 grid(Mrows / 64, (Vc + 63) / 64);
        gemm_f16_logits<<<grid, 128>>>(hf, emb_h, emb_l, logits,
                                       Mrows, Vc, Dc, Dc, Dc, Vc);
    }

    (void)in_sizes; (void)n_in; (void)out_size;
}

// round 16
// speedup vs baseline: 1.2630x; 1.2630x over previous
#include <cuda_runtime.h>
#include <cuda_bf16.h>
#include <cuda_fp16.h>
#include <math.h>
#include <stdint.h>

// Problem constants
#define Lc 12
#define Bc 2
#define Tc 448
#define Dc 768
#define Hc 12
#define Vc 51865
#define NCc 448
#define CTc 1500
#define HD 64
#define Mrows (Bc*Tc)      // 896
#define DDm (Dc*Dc)
#define D4 (4*Dc)          // 3072
#define D3 (3*Dc)          // 2304
#define XSPL 4
#define XTPS 6
#define FLDK (HD + 8)                       // 72
#define FSZ (64 * FLDK)                     // halves per tile buffer
#define FLASH_SMEM (2 * 4 * FSZ * 2)        // 2 stages x 4 bufs x halves x 2B = 73728

typedef __nv_bfloat16 bf16;

// -------------------- scratch (static device globals) -----------------------
__device__ __half s_Wqkv_h[(long)Lc*Dc*D3], s_Wqkv_l[(long)Lc*Dc*D3];
__device__ __half s_Wo_h[Lc*DDm],  s_Wo_l[Lc*DDm];
__device__ __half s_xWq_h[Lc*DDm], s_xWq_l[Lc*DDm];
__device__ __half s_xWo_h[Lc*DDm], s_xWo_l[Lc*DDm];
__device__ __half s_W1_h[(long)Lc*Dc*D4], s_W1_l[(long)Lc*Dc*D4];
__device__ __half s_W2_h[(long)Lc*Dc*D4], s_W2_l[(long)Lc*Dc*D4];
__device__ __half s_emb_h[(long)Vc*Dc], s_emb_l[(long)Vc*Dc];
__device__ __half s_ck_h[(long)Lc*Bc*CTc*Dc], s_ck_l[(long)Lc*Bc*CTc*Dc];
__device__ __half s_cv_h[(long)Lc*Bc*CTc*Dc], s_cv_l[(long)Lc*Bc*CTc*Dc];
// activations
__device__ float g_x[Mrows*Dc];
__device__ __half a_hf[Mrows*Dc];
__device__ __half a_atf[Mrows*Dc];
__device__ __half a_hidf[Mrows*D4];
__device__ __half a_qf[Mrows*Dc];
__device__ __half a_k_h[Mrows*Dc], a_k_l[Mrows*Dc];
__device__ __half a_v_h[Mrows*Dc], a_v_l[Mrows*Dc];
// split-K flash partials
__device__ float p_O[(long)XSPL * Bc*Hc * Tc * HD];
__device__ float p_m[XSPL * Bc*Hc * Tc];
__device__ float p_l[XSPL * Bc*Hc * Tc];

// -------------------- small helpers ----------------------------------------
__device__ __forceinline__ void cpa16(void* dst, const void* src, int bytes) {
    uint32_t d = (uint32_t)__cvta_generic_to_shared(dst);
    asm volatile("cp.async.cg.shared.global [%0], [%1], 16, %2;\n"
                 :: "r"(d), "l"(src), "r"(bytes));
}
__device__ __forceinline__ void cp_commit() { asm volatile("cp.async.commit_group;\n"); }
__device__ __forceinline__ void cp_wait0()  { asm volatile("cp.async.wait_group 0;\n"); }
__device__ __forceinline__ void cp_wait1()  { asm volatile("cp.async.wait_group 1;\n"); }

__device__ __forceinline__ void ldm4(uint32_t* r, const void* p) {
    uint32_t a = (uint32_t)__cvta_generic_to_shared(p);
    asm volatile("ldmatrix.sync.aligned.m8n8.x4.shared.b16 {%0,%1,%2,%3}, [%4];"
                 : "=r"(r[0]), "=r"(r[1]), "=r"(r[2]), "=r"(r[3]) : "r"(a));
}
__device__ __forceinline__ void ldm4t(uint32_t* r, const void* p) {
    uint32_t a = (uint32_t)__cvta_generic_to_shared(p);
    asm volatile("ldmatrix.sync.aligned.m8n8.x4.trans.shared.b16 {%0,%1,%2,%3}, [%4];"
                 : "=r"(r[0]), "=r"(r[1]), "=r"(r[2]), "=r"(r[3]) : "r"(a));
}
__device__ __forceinline__ void mma16816h(float* d, const uint32_t* a, const uint32_t* b) {
    asm volatile("mma.sync.aligned.m16n8k16.row.col.f32.f16.f16.f32 "
                 "{%0,%1,%2,%3}, {%4,%5,%6,%7}, {%8,%9}, {%0,%1,%2,%3};"
                 : "+f"(d[0]), "+f"(d[1]), "+f"(d[2]), "+f"(d[3])
                 : "r"(a[0]), "r"(a[1]), "r"(a[2]), "r"(a[3]), "r"(b[0]), "r"(b[1]));
}
__device__ __forceinline__ uint32_t packh(float x, float y) {
    __half2 h = __floats2half2_rn(x, y);
    return *(uint32_t*)&h;
}

// -------------------- conversions -------------------------------------------
__global__ void split4h_kernel(const float4* __restrict__ src,
                               __half2* __restrict__ h2,
                               __half2* __restrict__ l2, long n4) {
    long i = (long)blockIdx.x * blockDim.x + threadIdx.x;
    if (i >= n4) return;
    float4 v = src[i];
    __half h0 = __float2half(v.x), h1 = __float2half(v.y);
    __half h2v = __float2half(v.z), h3 = __float2half(v.w);
    h2[2*i]   = __half2(h0, h1);
    h2[2*i+1] = __half2(h2v, h3);
    l2[2*i]   = __half2(__float2half(v.x - __half2float(h0)),
                        __float2half(v.y - __half2float(h1)));
    l2[2*i+1] = __half2(__float2half(v.z - __half2float(h2v)),
                        __float2half(v.w - __half2float(h3)));
}

// merged strided fp16 split: Wq,Wk,Wv -> [L][768][2304] hi/lo
__global__ void split_qkv3h_kernel(const float4* __restrict__ sq,
                                   const float4* __restrict__ sk,
                                   const float4* __restrict__ sv,
                                   __half2* __restrict__ h2,
                                   __half2* __restrict__ l2, long n4) {
    long i = (long)blockIdx.x * blockDim.x + threadIdx.x;
    if (i >= n4) return;
    const float4* src = (blockIdx.y == 0) ? sq : (blockIdx.y == 1) ? sk : sv;
    int dstoff4 = blockIdx.y * 192;
    long row = i / 192;
    int c4 = (int)(i - row * 192);
    long d4 = row * 576 + dstoff4 + c4;
    float4 v = src[i];
    __half h0 = __float2half(v.x), h1 = __float2half(v.y);
    __half h2v = __float2half(v.z), h3 = __float2half(v.w);
    h2[2*d4]   = __half2(h0, h1);
    h2[2*d4+1] = __half2(h2v, h3);
    l2[2*d4]   = __half2(__float2half(v.x - __half2float(h0)),
                         __float2half(v.y - __half2float(h1)));
    l2[2*d4+1] = __half2(__float2half(v.z - __half2float(h2v)),
                         __float2half(v.w - __half2float(h3)));
}

// -------------------- reductions --------------------------------------------
__device__ __forceinline__ float blk_sum(float v) {
    __shared__ float s[32];
    int lane = threadIdx.x & 31, warp = threadIdx.x >> 5;
    #pragma unroll
    for (int o = 16; o > 0; o >>= 1) v += __shfl_down_sync(0xffffffffu, v, o);
    if (lane == 0) s[warp] = v;
    __syncthreads();
    int nw = blockDim.x >> 5;
    v = (threadIdx.x < nw) ? s[threadIdx.x] : 0.f;
    if (warp == 0) {
        #pragma unroll
        for (int o = 16; o > 0; o >>= 1) v += __shfl_down_sync(0xffffffffu, v, o);
        if (lane == 0) s[0] = v;
    }
    __syncthreads();
    float r = s[0];
    __syncthreads();
    return r;
}

// -------------------- embed / ln --------------------------------------------
__global__ void embed_kernel(const int* __restrict__ tokens,
                             const float* __restrict__ tokemb,
                             const float* __restrict__ pos,
                             float* __restrict__ x) {
    int row = blockIdx.x;
    int t = row % Tc;
    int tok = tokens[row];
    const float* te = tokemb + (long)tok * Dc;
    const float* pe = pos + (long)t * Dc;
    float* out = x + (long)row * Dc;
    for (int d = threadIdx.x; d < Dc; d += blockDim.x)
        out[d] = te[d] + pe[d];
}

__global__ void ln_half_kernel(const float* __restrict__ x,
                               __half* __restrict__ oh,
                               const float* __restrict__ g, const float* __restrict__ b) {
    const float* row = x + (long)blockIdx.x * Dc;
    long base = (long)blockIdx.x * Dc;
    int tid = threadIdx.x;
    float v0 = row[tid], v1 = row[tid + 256], v2 = row[tid + 512];
    float s  = blk_sum(v0 + v1 + v2);
    float s2 = blk_sum(v0*v0 + v1*v1 + v2*v2);
    float mean = s * (1.f / (float)Dc);
    float var = s2 * (1.f / (float)Dc) - mean * mean;
    float inv = rsqrtf(var + 1e-5f);
    #pragma unroll
    for (int j = 0; j < 3; j++) {
        int d = tid + j * 256;
        float v = (j == 0) ? v0 : (j == 1) ? v1 : v2;
        oh[base + d] = __float2half((v - mean) * inv * g[d] + b[d]);
    }
}

// -------------------- flash (fp16 2-term; double-buffered K/V) ---------------
// dynamic smem: stage s in {0,1}: Kh | Kl | Vh | Vl, each FSZ halves.
template<int CAUSAL>
__global__ __launch_bounds__(128)
void flash_kernel(const __half* __restrict__ Q,
                  const __half* __restrict__ Kh, const __half* __restrict__ Kl,
                  const __half* __restrict__ Vh, const __half* __restrict__ Vl,
                  __half* __restrict__ O,
                  int kvlen, int kvrows) {
    extern __shared__ __half fsm[];
    int z = blockIdx.z;
    int b = z / Hc, h = z - b * Hc;
    int qt = blockIdx.y;
    int q0 = qt * 64;
    long qoff = (long)b * Tc * Dc + h * HD;
    long koff = (long)b * kvrows * Dc + h * HD;
    Q += qoff; O += qoff;
    Kh += koff; Kl += koff; Vh += koff; Vl += koff;

    int tid = threadIdx.x, lane = tid & 31, warp = tid >> 5;

    // stage Q through stage-0 Kh buffer
    #pragma unroll
    for (int i = 0; i < 4; i++) {
        int idx = i * 128 + tid;
        int row = idx >> 3, c = (idx & 7) * 8;
        cpa16(&fsm[row * FLDK + c], Q + (long)(q0 + row) * Dc + c, 16);
    }
    cp_commit(); cp_wait0();
    __syncthreads();
    uint32_t qf[4][4];
    #pragma unroll
    for (int kc = 0; kc < 4; kc++)
        ldm4(qf[kc], &fsm[(warp*16 + (lane & 15)) * FLDK + kc*16 + (lane >> 4) * 8]);
    __syncthreads();

    float m0 = -1e30f, m1 = -1e30f, l0 = 0.f, l1 = 0.f;
    float oacc[8][4] = {};

    int ntile = CAUSAL ? (qt + 1) : ((kvlen + 63) >> 6);
    int qrow0 = q0 + warp*16 + (lane >> 2);
    int qrow1 = qrow0 + 8;

    auto load_tile = [&](int s, int j) {
        __half* kh = fsm + (s*4 + 0) * FSZ;
        __half* kl = fsm + (s*4 + 1) * FSZ;
        __half* vh = fsm + (s*4 + 2) * FSZ;
        __half* vl = fsm + (s*4 + 3) * FSZ;
        int k0 = j * 64;
        #pragma unroll
        for (int i = 0; i < 4; i++) {
            int idx = i * 128 + tid;
            int row = idx >> 3, c = (idx & 7) * 8;
            int inb = (k0 + row < kvlen);
            int bytes = inb ? 16 : 0;
            long off = inb ? ((long)(k0 + row) * Dc + c) : 0;
            cpa16(&kh[row * FLDK + c], Kh + off, bytes);
            cpa16(&kl[row * FLDK + c], Kl + off, bytes);
            cpa16(&vh[row * FLDK + c], Vh + off, bytes);
            cpa16(&vl[row * FLDK + c], Vl + off, bytes);
        }
    };

    load_tile(0, 0); cp_commit();

    for (int j = 0; j < ntile; j++) {
        int s = j & 1;
        if (j + 1 < ntile) { load_tile(s ^ 1, j + 1); cp_commit(); cp_wait1(); }
        else cp_wait0();
        __syncthreads();

        const __half* skh = fsm + (s*4 + 0) * FSZ;
        const __half* skl = fsm + (s*4 + 1) * FSZ;
        const __half* svh = fsm + (s*4 + 2) * FSZ;
        const __half* svl = fsm + (s*4 + 3) * FSZ;
        int k0 = j * 64;

        // S = Q @ K^T (2-term)
        float sreg[8][4] = {};
        #pragma unroll
        for (int kc = 0; kc < 4; kc++) {
            uint32_t bh[8][2], bl[8][2];
            #pragma unroll
            for (int nf2 = 0; nf2 < 4; nf2++) {
                uint32_t r[4];
                ldm4(r, &skh[(nf2*16 + (lane & 15)) * FLDK + kc*16 + (lane >> 4) * 8]);
                bh[2*nf2][0] = r[0]; bh[2*nf2+1][0] = r[1];
                bh[2*nf2][1] = r[2]; bh[2*nf2+1][1] = r[3];
                ldm4(r, &skl[(nf2*16 + (lane & 15)) * FLDK + kc*16 + (lane >> 4) * 8]);
                bl[2*nf2][0] = r[0]; bl[2*nf2+1][0] = r[1];
                bl[2*nf2][1] = r[2]; bl[2*nf2+1][1] = r[3];
            }
            #pragma unroll
            for (int nf = 0; nf < 8; nf++) {
                mma16816h(sreg[nf], qf[kc], bh[nf]);
                mma16816h(sreg[nf], qf[kc], bl[nf]);
            }
        }

        // scale + mask
        #pragma unroll
        for (int nf = 0; nf < 8; nf++) {
            #pragma unroll
            for (int e = 0; e < 4; e++) {
                int col = k0 + nf*8 + (lane & 3)*2 + (e & 1);
                int qr = (e < 2) ? qrow0 : qrow1;
                bool ok = (col < kvlen) && (!CAUSAL || col <= qr);
                sreg[nf][e] = ok ? (sreg[nf][e] * 0.125f) : -1e30f;
            }
        }

        // online softmax
        float rm0 = -1e30f, rm1 = -1e30f;
        #pragma unroll
        for (int nf = 0; nf < 8; nf++) {
            rm0 = fmaxf(rm0, fmaxf(sreg[nf][0], sreg[nf][1]));
            rm1 = fmaxf(rm1, fmaxf(sreg[nf][2], sreg[nf][3]));
        }
        rm0 = fmaxf(rm0, __shfl_xor_sync(0xffffffffu, rm0, 1));
        rm0 = fmaxf(rm0, __shfl_xor_sync(0xffffffffu, rm0, 2));
        rm1 = fmaxf(rm1, __shfl_xor_sync(0xffffffffu, rm1, 1));
        rm1 = fmaxf(rm1, __shfl_xor_sync(0xffffffffu, rm1, 2));
        float mn0 = fmaxf(m0, rm0), mn1 = fmaxf(m1, rm1);
        float f0 = __expf(m0 - mn0), f1 = __expf(m1 - mn1);
        float rs0 = 0.f, rs1 = 0.f;
        #pragma unroll
        for (int nf = 0; nf < 8; nf++) {
            float p0 = __expf(sreg[nf][0] - mn0);
            float p1 = __expf(sreg[nf][1] - mn0);
            float p2 = __expf(sreg[nf][2] - mn1);
            float p3 = __expf(sreg[nf][3] - mn1);
            sreg[nf][0] = p0; sreg[nf][1] = p1; sreg[nf][2] = p2; sreg[nf][3] = p3;
            rs0 += p0 + p1;
            rs1 += p2 + p3;
        }
        rs0 += __shfl_xor_sync(0xffffffffu, rs0, 1);
        rs0 += __shfl_xor_sync(0xffffffffu, rs0, 2);
        rs1 += __shfl_xor_sync(0xffffffffu, rs1, 1);
        rs1 += __shfl_xor_sync(0xffffffffu, rs1, 2);
        l0 = l0 * f0 + rs0;
        l1 = l1 * f1 + rs1;
        m0 = mn0; m1 = mn1;
        #pragma unroll
        for (int nf = 0; nf < 8; nf++) {
            oacc[nf][0] *= f0; oacc[nf][1] *= f0;
            oacc[nf][2] *= f1; oacc[nf][3] *= f1;
        }

        // P frags (single fp16)
        uint32_t pa[4][4];
        #pragma unroll
        for (int kc = 0; kc < 4; kc++) {
            pa[kc][0] = packh(sreg[2*kc][0],   sreg[2*kc][1]);
            pa[kc][1] = packh(sreg[2*kc][2],   sreg[2*kc][3]);
            pa[kc][2] = packh(sreg[2*kc+1][0], sreg[2*kc+1][1]);
            pa[kc][3] = packh(sreg[2*kc+1][2], sreg[2*kc+1][3]);
        }

        // O += P @ V (2-term)
        #pragma unroll
        for (int kk = 0; kk < 4; kk++) {
            uint32_t vfh[8][2], vfl[8][2];
            #pragma unroll
            for (int nf2 = 0; nf2 < 4; nf2++) {
                uint32_t r[4];
                ldm4t(r, &svh[(kk*16 + (lane & 15)) * FLDK + nf2*16 + (lane >> 4) * 8]);
                vfh[2*nf2][0] = r[0]; vfh[2*nf2][1] = r[1];
                vfh[2*nf2+1][0] = r[2]; vfh[2*nf2+1][1] = r[3];
                ldm4t(r, &svl[(kk*16 + (lane & 15)) * FLDK + nf2*16 + (lane >> 4) * 8]);
                vfl[2*nf2][0] = r[0]; vfl[2*nf2][1] = r[1];
                vfl[2*nf2+1][0] = r[2]; vfl[2*nf2+1][1] = r[3];
            }
            #pragma unroll
            for (int nf = 0; nf < 8; nf++) {
                mma16816h(oacc[nf], pa[kk], vfh[nf]);
                mma16816h(oacc[nf], pa[kk], vfl[nf]);
            }
        }
        __syncthreads();
    }

    float il0 = 1.f / l0, il1 = 1.f / l1;
    #pragma unroll
    for (int nf = 0; nf < 8; nf++) {
        int col = nf*8 + (lane & 3)*2;
        *(__half2*)&O[(long)qrow0 * Dc + col] =
            __floats2half2_rn(oacc[nf][0] * il0, oacc[nf][1] * il0);
        *(__half2*)&O[(long)qrow1 * Dc + col] =
            __floats2half2_rn(oacc[nf][2] * il1, oacc[nf][3] * il1);
    }
}

// -------------------- split-K flash (fp16 2-term, double-buffered) -----------
__global__ __launch_bounds__(128)
void flashp_kernel(const __half* __restrict__ Q,
                   const __half* __restrict__ Kh, const __half* __restrict__ Kl,
                   const __half* __restrict__ Vh, const __half* __restrict__ Vl,
                   float* __restrict__ pO, float* __restrict__ pm,
                   float* __restrict__ pl, int kvlen) {
    extern __shared__ __half fsm[];
    int sp = blockIdx.x;
    int z = blockIdx.z;
    int b = z / Hc, h = z - b * Hc;
    int qt = blockIdx.y;
    int q0 = qt * 64;
    long qoff = (long)b * Tc * Dc + h * HD;
    long koff = (long)b * CTc * Dc + h * HD;
    Q += qoff;
    Kh += koff; Kl += koff; Vh += koff; Vl += koff;

    int tid = threadIdx.x, lane = tid & 31, warp = tid >> 5;

    #pragma unroll
    for (int i = 0; i < 4; i++) {
        int idx = i * 128 + tid;
        int row = idx >> 3, c = (idx & 7) * 8;
        cpa16(&fsm[row * FLDK + c], Q + (long)(q0 + row) * Dc + c, 16);
    }
    cp_commit(); cp_wait0();
    __syncthreads();
    uint32_t qf[4][4];
    #pragma unroll
    for (int kc = 0; kc < 4; kc++)
        ldm4(qf[kc], &fsm[(warp*16 + (lane & 15)) * FLDK + kc*16 + (lane >> 4) * 8]);
    __syncthreads();

    float m0 = -1e30f, m1 = -1e30f, l0 = 0.f, l1 = 0.f;
    float oacc[8][4] = {};

    int jlo = sp * XTPS, jhi = jlo + XTPS;
    int qrow0 = q0 + warp*16 + (lane >> 2);
    int qrow1 = qrow0 + 8;

    auto load_tile = [&](int s, int j) {
        __half* kh = fsm + (s*4 + 0) * FSZ;
        __half* kl = fsm + (s*4 + 1) * FSZ;
        __half* vh = fsm + (s*4 + 2) * FSZ;
        __half* vl = fsm + (s*4 + 3) * FSZ;
        int k0 = j * 64;
        #pragma unroll
        for (int i = 0; i < 4; i++) {
            int idx = i * 128 + tid;
            int row = idx >> 3, c = (idx & 7) * 8;
            int inb = (k0 + row < kvlen);
            int bytes = inb ? 16 : 0;
            long off = inb ? ((long)(k0 + row) * Dc + c) : 0;
            cpa16(&kh[row * FLDK + c], Kh + off, bytes);
            cpa16(&kl[row * FLDK + c], Kl + off, bytes);
            cpa16(&vh[row * FLDK + c], Vh + off, bytes);
            cpa16(&vl[row * FLDK + c], Vl + off, bytes);
        }
    };

    load_tile(0, jlo); cp_commit();

    for (int j = jlo; j < jhi; j++) {
        int s = (j - jlo) & 1;
        if (j + 1 < jhi) { load_tile(s ^ 1, j + 1); cp_commit(); cp_wait1(); }
        else cp_wait0();
        __syncthreads();

        const __half* skh = fsm + (s*4 + 0) * FSZ;
        const __half* skl = fsm + (s*4 + 1) * FSZ;
        const __half* svh = fsm + (s*4 + 2) * FSZ;
        const __half* svl = fsm + (s*4 + 3) * FSZ;
        int k0 = j * 64;

        float sreg[8][4] = {};
        #pragma unroll
        for (int kc = 0; kc < 4; kc++) {
            uint32_t bh[8][2], bl[8][2];
            #pragma unroll
            for (int nf2 = 0; nf2 < 4; nf2++) {
                uint32_t r[4];
                ldm4(r, &skh[(nf2*16 + (lane & 15)) * FLDK + kc*16 + (lane >> 4) * 8]);
                bh[2*nf2][0] = r[0]; bh[2*nf2+1][0] = r[1];
                bh[2*nf2][1] = r[2]; bh[2*nf2+1][1] = r[3];
                ldm4(r, &skl[(nf2*16 + (lane & 15)) * FLDK + kc*16 + (lane >> 4) * 8]);
                bl[2*nf2][0] = r[0]; bl[2*nf2+1][0] = r[1];
                bl[2*nf2][1] = r[2]; bl[2*nf2+1][1] = r[3];
            }
            #pragma unroll
            for (int nf = 0; nf < 8; nf++) {
                mma16816h(sreg[nf], qf[kc], bh[nf]);
                mma16816h(sreg[nf], qf[kc], bl[nf]);
            }
        }

        #pragma unroll
        for (int nf = 0; nf < 8; nf++) {
            #pragma unroll
            for (int e = 0; e < 4; e++) {
                int col = k0 + nf*8 + (lane & 3)*2 + (e & 1);
                sreg[nf][e] = (col < kvlen) ? (sreg[nf][e] * 0.125f) : -1e30f;
            }
        }

        float rm0 = -1e30f, rm1 = -1e30f;
        #pragma unroll
        for (int nf = 0; nf < 8; nf++) {
            rm0 = fmaxf(rm0, fmaxf(sreg[nf][0], sreg[nf][1]));
            rm1 = fmaxf(rm1, fmaxf(sreg[nf][2], sreg[nf][3]));
        }
        rm0 = fmaxf(rm0, __shfl_xor_sync(0xffffffffu, rm0, 1));
        rm0 = fmaxf(rm0, __shfl_xor_sync(0xffffffffu, rm0, 2));
        rm1 = fmaxf(rm1, __shfl_xor_sync(0xffffffffu, rm1, 1));
        rm1 = fmaxf(rm1, __shfl_xor_sync(0xffffffffu, rm1, 2));
        float mn0 = fmaxf(m0, rm0), mn1 = fmaxf(m1, rm1);
        float f0 = __expf(m0 - mn0), f1 = __expf(m1 - mn1);
        float rs0 = 0.f, rs1 = 0.f;
        #pragma unroll
        for (int nf = 0; nf < 8; nf++) {
            float p0 = __expf(sreg[nf][0] - mn0);
            float p1 = __expf(sreg[nf][1] - mn0);
            float p2 = __expf(sreg[nf][2] - mn1);
            float p3 = __expf(sreg[nf][3] - mn1);
            sreg[nf][0] = p0; sreg[nf][1] = p1; sreg[nf][2] = p2; sreg[nf][3] = p3;
            rs0 += p0 + p1;
            rs1 += p2 + p3;
        }
        rs0 += __shfl_xor_sync(0xffffffffu, rs0, 1);
        rs0 += __shfl_xor_sync(0xffffffffu, rs0, 2);
        rs1 += __shfl_xor_sync(0xffffffffu, rs1, 1);
        rs1 += __shfl_xor_sync(0xffffffffu, rs1, 2);
        l0 = l0 * f0 + rs0;
        l1 = l1 * f1 + rs1;
        m0 = mn0; m1 = mn1;
        #pragma unroll
        for (int nf = 0; nf < 8; nf++) {
            oacc[nf][0] *= f0; oacc[nf][1] *= f0;
            oacc[nf][2] *= f1; oacc[nf][3] *= f1;
        }

        uint32_t pa[4][4];
        #pragma unroll
        for (int kc = 0; kc < 4; kc++) {
            pa[kc][0] = packh(sreg[2*kc][0],   sreg[2*kc][1]);
            pa[kc][1] = packh(sreg[2*kc][2],   sreg[2*kc][3]);
            pa[kc][2] = packh(sreg[2*kc+1][0], sreg[2*kc+1][1]);
            pa[kc][3] = packh(sreg[2*kc+1][2], sreg[2*kc+1][3]);
        }

        #pragma unroll
        for (int kk = 0; kk < 4; kk++) {
            uint32_t vfh[8][2], vfl[8][2];
            #pragma unroll
            for (int nf2 = 0; nf2 < 4; nf2++) {
                uint32_t r[4];
                ldm4t(r, &svh[(kk*16 + (lane & 15)) * FLDK + nf2*16 + (lane >> 4) * 8]);
                vfh[2*nf2][0] = r[0]; vfh[2*nf2][1] = r[1];
                vfh[2*nf2+1][0] = r[2]; vfh[2*nf2+1][1] = r[3];
                ldm4t(r, &svl[(kk*16 + (lane & 15)) * FLDK + nf2*16 + (lane >> 4) * 8]);
                vfl[2*nf2][0] = r[0]; vfl[2*nf2][1] = r[1];
                vfl[2*nf2+1][0] = r[2]; vfl[2*nf2+1][1] = r[3];
            }
            #pragma unroll
            for (int nf = 0; nf < 8; nf++) {
                mma16816h(oacc[nf], pa[kk], vfh[nf]);
                mma16816h(oacc[nf], pa[kk], vfl[nf]);
            }
        }
        __syncthreads();
    }

    long base = ((long)sp * (Bc*Hc) + z) * Tc;
    if ((lane & 3) == 0) {
        pm[base + qrow0] = m0; pl[base + qrow0] = l0;
        pm[base + qrow1] = m1; pl[base + qrow1] = l1;
    }
    #pragma unroll
    for (int nf = 0; nf < 8; nf++) {
        int col = nf*8 + (lane & 3)*2;
        float2* d0 = (float2*)&pO[(base + qrow0) * HD + col];
        float2* d1 = (float2*)&pO[(base + qrow1) * HD + col];
        *d0 = make_float2(oacc[nf][0], oacc[nf][1]);
        *d1 = make_float2(oacc[nf][2], oacc[nf][3]);
    }
}

__global__ void flashc_kernel(const float* __restrict__ pO,
                              const float* __restrict__ pm,
                              const float* __restrict__ pl,
                              __half* __restrict__ O) {
    int row = blockIdx.x, z = blockIdx.y, c = threadIdx.x;
    int b = z / Hc, h = z - b * Hc;
    float ms[XSPL];
    float mstar = -1e30f;
    #pragma unroll
    for (int s = 0; s < XSPL; s++) {
        ms[s] = pm[((long)s * (Bc*Hc) + z) * Tc + row];
        mstar = fmaxf(mstar, ms[s]);
    }
    float osum = 0.f, lsum = 0.f;
    #pragma unroll
    for (int s = 0; s < XSPL; s++) {
        long base = ((long)s * (Bc*Hc) + z) * Tc + row;
        float w = __expf(ms[s] - mstar);
        lsum += w * pl[base];
        osum += w * pO[base * HD + c];
    }
    long oi = (long)b * Tc * Dc + (long)row * Dc + h * HD + c;
    O[oi] = __float2half(osum / lsum);
}

// -------------------- fp16 2-term GEMM (BM=64, TRANSB=0) --------------------
__global__ __launch_bounds__(128)
void gemm_h2(const __half* __restrict__ A,
             const __half* __restrict__ Bh, const __half* __restrict__ Bl,
             float* Cf, __half* Chf,
             const float* __restrict__ bias,
             int M, int N, int K, int lda, int ldb, int ldc, int mode) {
    constexpr int BM = 64, BN = 64, BK = 32;
    constexpr int LDA = BK + 8, LDB = BN + 8;

    __shared__ __half sA[2][BM * LDA];
    __shared__ __half sB[2][2][BK * LDB];

    int tid = threadIdx.x;
    int lane = tid & 31, warp = tid >> 5;
    int wm = warp >> 1, wn = warp & 1;
    int m0 = blockIdx.x * BM, n0 = blockIdx.y * BN;

    auto load_stage = [&](int s, int kt) {
        int k0 = kt * BK;
        #pragma unroll
        for (int i = 0; i < 2; i++) {
            int idx = i * 128 + tid;
            int row = idx >> 2, kc = (idx & 3) * 8;
            cpa16(&sA[s][row * LDA + kc], A + (long)(m0 + row) * lda + k0 + kc, 16);
        }
        #pragma unroll
        for (int i = 0; i < 2; i++) {
            int idx = i * 128 + tid;
            int krow = idx >> 3, nc = (idx & 7) * 8;
            long off = (long)(k0 + krow) * ldb + n0 + nc;
            cpa16(&sB[s][0][krow * LDB + nc], Bh + off, 16);
            cpa16(&sB[s][1][krow * LDB + nc], Bl + off, 16);
        }
    };

    float acc[2][4][4] = {};
    int KT = K / BK;

    load_stage(0, 0);
    cp_commit();

    for (int kt = 0; kt < KT; kt++) {
        int cur = kt & 1;
        bool more = (kt + 1 < KT);
        if (more) { load_stage(cur ^ 1, kt + 1); cp_commit(); }
        if (more) cp_wait1(); else cp_wait0();
        __syncthreads();

        #pragma unroll
        for (int kf = 0; kf < 2; kf++) {
            uint32_t ah[2][4];
            #pragma unroll
            for (int mf = 0; mf < 2; mf++)
                ldm4(ah[mf], &sA[cur][(wm*32 + mf*16 + (lane & 15)) * LDA + kf*16 + (lane >> 4) * 8]);
            uint32_t bh[4][2], bl[4][2];
            #pragma unroll
            for (int nf2 = 0; nf2 < 2; nf2++) {
                uint32_t r[4];
                ldm4t(r, &sB[cur][0][(kf*16 + (lane & 15)) * LDB + wn*32 + nf2*16 + (lane >> 4) * 8]);
                bh[2*nf2][0] = r[0]; bh[2*nf2][1] = r[1];
                bh[2*nf2+1][0] = r[2]; bh[2*nf2+1][1] = r[3];
                ldm4t(r, &sB[cur][1][(kf*16 + (lane & 15)) * LDB + wn*32 + nf2*16 + (lane >> 4) * 8]);
                bl[2*nf2][0] = r[0]; bl[2*nf2][1] = r[1];
                bl[2*nf2+1][0] = r[2]; bl[2*nf2+1][1] = r[3];
            }
            #pragma unroll
            for (int mf = 0; mf < 2; mf++)
                #pragma unroll
                for (int nf = 0; nf < 4; nf++) {
                    mma16816h(acc[mf][nf], ah[mf], bh[nf]);
                    mma16816h(acc[mf][nf], ah[mf], bl[nf]);
                }
        }
        __syncthreads();
    }

    int r = lane >> 2, c = (lane & 3) * 2;
    #pragma unroll
    for (int mf = 0; mf < 2; mf++) {
        #pragma unroll
        for (int i = 0; i < 2; i++) {
            int grow = m0 + wm*32 + mf*16 + r + i*8;
            #pragma unroll
            for (int nf = 0; nf < 4; nf++) {
                #pragma unroll
                for (int j = 0; j < 2; j++) {
                    int gcol = n0 + wn*32 + nf*8 + c + j;
                    float v = acc[mf][nf][i*2 + j];
                    long ci = (long)grow * ldc + gcol;
                    if (mode >= 1) v += bias[gcol];
                    if (mode == 2) v += Cf[ci];
                    if (mode == 3) v = 0.5f * v * (1.f + erff(v * 0.70710678118654752f));
                    if (Cf) Cf[ci] = v;
                    if (Chf) Chf[ci] = __float2half(v);
                }
            }
        }
    }
}

// -------------------- fp16 2-term small-tile GEMM (BM=32) -------------------
__global__ __launch_bounds__(128)
void gemm_h2_sm(const __half* __restrict__ A,
                const __half* __restrict__ Bh, const __half* __restrict__ Bl,
                float* Cf, __half* Chf,
                const float* __restrict__ bias,
                int M, int N, int K, int lda, int ldb, int ldc, int mode) {
    constexpr int BM = 32, BN = 64, BK = 32;
    constexpr int LDA = BK + 8, LDB = BN + 8;

    __shared__ __half sA[2][BM * LDA];
    __shared__ __half sB[2][2][BK * LDB];

    int tid = threadIdx.x;
    int lane = tid & 31, wn = tid >> 5;
    int m0 = blockIdx.x * BM, n0 = blockIdx.y * BN;

    auto load_stage = [&](int s, int kt) {
        int k0 = kt * BK;
        {
            int row = tid >> 2, kc = (tid & 3) * 8;
            cpa16(&sA[s][row * LDA + kc], A + (long)(m0 + row) * lda + k0 + kc, 16);
        }
        #pragma unroll
        for (int i = 0; i < 2; i++) {
            int idx = i * 128 + tid;
            int krow = idx >> 3, nc = (idx & 7) * 8;
            long off = (long)(k0 + krow) * ldb + n0 + nc;
            cpa16(&sB[s][0][krow * LDB + nc], Bh + off, 16);
            cpa16(&sB[s][1][krow * LDB + nc], Bl + off, 16);
        }
    };

    float acc[2][2][4] = {};
    int KT = K / BK;

    load_stage(0, 0);
    cp_commit();

    for (int kt = 0; kt < KT; kt++) {
        int cur = kt & 1;
        bool more = (kt + 1 < KT);
        if (more) { load_stage(cur ^ 1, kt + 1); cp_commit(); }
        if (more) cp_wait1(); else cp_wait0();
        __syncthreads();

        #pragma unroll
        for (int kf = 0; kf < 2; kf++) {
            uint32_t ah[2][4];
            #pragma unroll
            for (int mf = 0; mf < 2; mf++)
                ldm4(ah[mf], &sA[cur][(mf*16 + (lane & 15)) * LDA + kf*16 + (lane >> 4) * 8]);
            uint32_t bh[2][2], bl[2][2];
            {
                uint32_t r[4];
                ldm4t(r, &sB[cur][0][(kf*16 + (lane & 15)) * LDB + wn*16 + (lane >> 4) * 8]);
                bh[0][0] = r[0]; bh[0][1] = r[1];
                bh[1][0] = r[2]; bh[1][1] = r[3];
                ldm4t(r, &sB[cur][1][(kf*16 + (lane & 15)) * LDB + wn*16 + (lane >> 4) * 8]);
                bl[0][0] = r[0]; bl[0][1] = r[1];
                bl[1][0] = r[2]; bl[1][1] = r[3];
            }
            #pragma unroll
            for (int mf = 0; mf < 2; mf++)
                #pragma unroll
                for (int nf = 0; nf < 2; nf++) {
                    mma16816h(acc[mf][nf], ah[mf], bh[nf]);
                    mma16816h(acc[mf][nf], ah[mf], bl[nf]);
                }
        }
        __syncthreads();
    }

    int r = lane >> 2, c = (lane & 3) * 2;
    #pragma unroll
    for (int mf = 0; mf < 2; mf++) {
        #pragma unroll
        for (int i = 0; i < 2; i++) {
            int grow = m0 + mf*16 + r + i*8;
            #pragma unroll
            for (int nf = 0; nf < 2; nf++) {
                #pragma unroll
                for (int j = 0; j < 2; j++) {
                    int gcol = n0 + wn*16 + nf*8 + c + j;
                    float v = acc[mf][nf][i*2 + j];
                    long ci = (long)grow * ldc + gcol;
                    if (mode >= 1) v += bias[gcol];
                    if (mode == 2) v += Cf[ci];
                    if (mode == 3) v = 0.5f * v * (1.f + erff(v * 0.70710678118654752f));
                    if (Cf) Cf[ci] = v;
                    if (Chf) Chf[ci] = __float2half(v);
                }
            }
        }
    }
}

// -------------------- fp16 fused QKV GEMM ------------------------------------
// region 0: q -> single fp16; 1: k -> cache fp32 + fp16 hi/lo; 2: v likewise + bias
__global__ __launch_bounds__(128)
void gemm_qkv_h2(const __half* __restrict__ A,
                 const __half* __restrict__ Bh, const __half* __restrict__ Bl,
                 const float* __restrict__ bq, const float* __restrict__ bv,
                 __half* __restrict__ qf,
                 __half* __restrict__ kh, __half* __restrict__ kl,
                 __half* __restrict__ vh, __half* __restrict__ vl,
                 float* __restrict__ kcache, float* __restrict__ vcache) {
    constexpr int BM = 64, BN = 64, BK = 32;
    constexpr int LDA = BK + 8, LDB = BN + 8;
    const int K = Dc, ldb = D3, lda = Dc;

    __shared__ __half sA[2][BM * LDA];
    __shared__ __half sB[2][2][BK * LDB];

    int tid = threadIdx.x;
    int lane = tid & 31, warp = tid >> 5;
    int wm = warp >> 1, wn = warp & 1;
    int m0 = blockIdx.x * BM, n0 = blockIdx.y * BN;

    int reg = n0 / Dc;
    int cn0 = n0 - reg * Dc;
    const float* bias = (reg == 0) ? bq : (reg == 2 ? bv : nullptr);
    float* Cf = (reg == 1) ? kcache : (reg == 2 ? vcache : nullptr);
    __half* Ch = (reg == 1) ? kh : vh;
    __half* Cl = (reg == 1) ? kl : vl;

    auto load_stage = [&](int s, int kt) {
        int k0 = kt * BK;
        #pragma unroll
        for (int i = 0; i < 2; i++) {
            int idx = i * 128 + tid;
            int row = idx >> 2, kc = (idx & 3) * 8;
            cpa16(&sA[s][row * LDA + kc], A + (long)(m0 + row) * lda + k0 + kc, 16);
        }
        #pragma unroll
        for (int i = 0; i < 2; i++) {
            int idx = i * 128 + tid;
            int krow = idx >> 3, nc = (idx & 7) * 8;
            long off = (long)(k0 + krow) * ldb + n0 + nc;
            cpa16(&sB[s][0][krow * LDB + nc], Bh + off, 16);
            cpa16(&sB[s][1][krow * LDB + nc], Bl + off, 16);
        }
    };

    float acc[2][4][4] = {};
    int KT = K / BK;

    load_stage(0, 0);
    cp_commit();

    for (int kt = 0; kt < KT; kt++) {
        int cur = kt & 1;
        bool more = (kt + 1 < KT);
        if (more) { load_stage(cur ^ 1, kt + 1); cp_commit(); }
        if (more) cp_wait1(); else cp_wait0();
        __syncthreads();

        #pragma unroll
        for (int kf = 0; kf < 2; kf++) {
            uint32_t ah[2][4];
            #pragma unroll
            for (int mf = 0; mf < 2; mf++)
                ldm4(ah[mf], &sA[cur][(wm*32 + mf*16 + (lane & 15)) * LDA + kf*16 + (lane >> 4) * 8]);
            uint32_t bh[4][2], bl[4][2];
            #pragma unroll
            for (int nf2 = 0; nf2 < 2; nf2++) {
                uint32_t r[4];
                ldm4t(r, &sB[cur][0][(kf*16 + (lane & 15)) * LDB + wn*32 + nf2*16 + (lane >> 4) * 8]);
                bh[2*nf2][0] = r[0]; bh[2*nf2][1] = r[1];
                bh[2*nf2+1][0] = r[2]; bh[2*nf2+1][1] = r[3];
                ldm4t(r, &sB[cur][1][(kf*16 + (lane & 15)) * LDB + wn*32 + nf2*16 + (lane >> 4) * 8]);
                bl[2*nf2][0] = r[0]; bl[2*nf2][1] = r[1];
                bl[2*nf2+1][0] = r[2]; bl[2*nf2+1][1] = r[3];
            }
            #pragma unroll
            for (int mf = 0; mf < 2; mf++)
                #pragma unroll
                for (int nf = 0; nf < 4; nf++) {
                    mma16816h(acc[mf][nf], ah[mf], bh[nf]);
                    mma16816h(acc[mf][nf], ah[mf], bl[nf]);
                }
        }
        __syncthreads();
    }

    int r = lane >> 2, c = (lane & 3) * 2;
    #pragma unroll
    for (int mf = 0; mf < 2; mf++) {
        #pragma unroll
        for (int i = 0; i < 2; i++) {
            int grow = m0 + wm*32 + mf*16 + r + i*8;
            #pragma unroll
            for (int nf = 0; nf < 4; nf++) {
                #pragma unroll
                for (int j = 0; j < 2; j++) {
                    int col = cn0 + wn*32 + nf*8 + c + j;
                    float v = acc[mf][nf][i*2 + j];
                    if (bias) v += bias[col];
                    long ci = (long)grow * Dc + col;
                    if (reg == 0) {
                        qf[ci] = __float2half(v);
                    } else {
                        Cf[ci] = v;
                        __half h = __float2half(v);
                        Ch[ci] = h;
                        Cl[ci] = __float2half(v - __half2float(h));
                    }
                }
            }
        }
    }
}

// -------------------- fp16 2-term logits GEMM (TRANSB=1) ---------------------
__global__ __launch_bounds__(128)
void gemm_f16_logits(const __half* __restrict__ A,
                     const __half* __restrict__ Bh, const __half* __restrict__ Bl,
                     float* __restrict__ Cf,
                     int M, int N, int K, int lda, int ldb, int ldc) {
    constexpr int BM = 64, BN = 64, BK = 32;
    constexpr int LDA = BK + 8, LDB = BK + 8;

    __shared__ __half sA[2][BM * LDA];
    __shared__ __half sB[2][2][BN * LDB];

    int tid = threadIdx.x;
    int lane = tid & 31, warp = tid >> 5;
    int wm = warp >> 1, wn = warp & 1;
    int m0 = blockIdx.x * BM, n0 = blockIdx.y * BN;

    auto load_stage = [&](int s, int kt) {
        int k0 = kt * BK;
        #pragma unroll
        for (int i = 0; i < 2; i++) {
            int idx = i * 128 + tid;
            int row = idx >> 2, kc = (idx & 3) * 8;
            cpa16(&sA[s][row * LDA + kc], A + (long)(m0 + row) * lda + k0 + kc, 16);
        }
        #pragma unroll
        for (int i = 0; i < 2; i++) {
            int idx = i * 128 + tid;
            int nrow = idx >> 2, kc = (idx & 3) * 8;
            int gn = n0 + nrow;
            int bytes = (gn < N) ? 16 : 0;
            long off = (long)(gn < N ? gn : 0) * ldb + k0 + kc;
            cpa16(&sB[s][0][nrow * LDB + kc], Bh + off, bytes);
            cpa16(&sB[s][1][nrow * LDB + kc], Bl + off, bytes);
        }
    };

    float acc[2][4][4] = {};
    int KT = K / BK;

    load_stage(0, 0);
    cp_commit();

    for (int kt = 0; kt < KT; kt++) {
        int cur = kt & 1;
        bool more = (kt + 1 < KT);
        if (more) { load_stage(cur ^ 1, kt + 1); cp_commit(); }
        if (more) cp_wait1(); else cp_wait0();
        __syncthreads();

        #pragma unroll
        for (int kf = 0; kf < 2; kf++) {
            uint32_t ah[2][4];
            #pragma unroll
            for (int mf = 0; mf < 2; mf++)
                ldm4(ah[mf], &sA[cur][(wm*32 + mf*16 + (lane & 15)) * LDA + kf*16 + (lane >> 4) * 8]);
            uint32_t bh[4][2], bl[4][2];
            #pragma unroll
            for (int nf2 = 0; nf2 < 2; nf2++) {
                uint32_t r[4];
                ldm4(r, &sB[cur][0][(wn*32 + nf2*16 + (lane & 15)) * LDB + kf*16 + (lane >> 4) * 8]);
                bh[2*nf2][0] = r[0]; bh[2*nf2+1][0] = r[1];
                bh[2*nf2][1] = r[2]; bh[2*nf2+1][1] = r[3];
                ldm4(r, &sB[cur][1][(wn*32 + nf2*16 + (lane & 15)) * LDB + kf*16 + (lane >> 4) * 8]);
                bl[2*nf2][0] = r[0]; bl[2*nf2+1][0] = r[1];
                bl[2*nf2][1] = r[2]; bl[2*nf2+1][1] = r[3];
            }
            #pragma unroll
            for (int mf = 0; mf < 2; mf++)
                #pragma unroll
                for (int nf = 0; nf < 4; nf++) {
                    mma16816h(acc[mf][nf], ah[mf], bh[nf]);
                    mma16816h(acc[mf][nf], ah[mf], bl[nf]);
                }
        }
        __syncthreads();
    }

    int r = lane >> 2, c = (lane & 3) * 2;
    #pragma unroll
    for (int mf = 0; mf < 2; mf++) {
        #pragma unroll
        for (int i = 0; i < 2; i++) {
            int grow = m0 + wm*32 + mf*16 + r + i*8;
            #pragma unroll
            for (int nf = 0; nf < 4; nf++) {
                #pragma unroll
                for (int j = 0; j < 2; j++) {
                    int gcol = n0 + wn*32 + nf*8 + c + j;
                    if (gcol >= N) continue;
                    Cf[(long)grow * ldc + gcol] = acc[mf][nf][i*2 + j];
                }
            }
        }
    }
}

// -------------------- host helpers ------------------------------------------
static inline void split_fp16(cudaStream_t st, const float* src, __half* h, __half* l, long n) {
    long n4 = n / 4;
    int blocks = (int)((n4 + 255) / 256);
    split4h_kernel<<<blocks, 256, 0, st>>>((const float4*)src, (__half2*)h,
                                           (__half2*)l, n4);
}
static inline void gh2(const __half* A, const __half* Bh, const __half* Bl,
                       float* Cf, __half* Chf, const float* bias,
                       int M, int N, int K, int lda, int ldb, int ldc, int mode) {
    dim3 grid(M / 64, N / 64);
    gemm_h2<<<grid, 128>>>(A, Bh, Bl, Cf, Chf, bias, M, N, K, lda, ldb, ldc, mode);
}
static inline void gh2_sm(const __half* A, const __half* Bh, const __half* Bl,
                          float* Cf, __half* Chf, const float* bias,
                          int M, int N, int K, int lda, int ldb, int ldc, int mode) {
    dim3 grid(M / 32, N / 64);
    gemm_h2_sm<<<grid, 128>>>(A, Bh, Bl, Cf, Chf, bias, M, N, K, lda, ldb, ldc, mode);
}

#define SYM(p, s) cudaGetSymbolAddress((void**)&p, s)

extern "C" void kernel_launch(void* const* d_in, const int* in_sizes, int n_in,
                              void* d_out, int out_size) {
    const int*   tokens    = (const int*)  d_in[0];
    const float* cross_k   = (const float*)d_in[3];
    const float* cross_v   = (const float*)d_in[4];
    const float* tokemb    = (const float*)d_in[6];
    const float* posemb    = (const float*)d_in[7];
    const float* attn_ln_g = (const float*)d_in[9];
    const float* attn_ln_b = (const float*)d_in[10];
    const float* Wq_all    = (const float*)d_in[11];
    const float* bq_all    = (const float*)d_in[12];
    const float* Wk_all    = (const float*)d_in[13];
    const float* Wv_all    = (const float*)d_in[14];
    const float* bv_all    = (const float*)d_in[15];
    const float* Wo_all    = (const float*)d_in[16];
    const float* bo_all    = (const float*)d_in[17];
    const float* xln_g     = (const float*)d_in[18];
    const float* xln_b     = (const float*)d_in[19];
    const float* xWq_all   = (const float*)d_in[20];
    const float* xbq_all   = (const float*)d_in[21];
    const float* xWo_all   = (const float*)d_in[22];
    const float* xbo_all   = (const float*)d_in[23];
    const float* mln_g     = (const float*)d_in[24];
    const float* mln_b     = (const float*)d_in[25];
    const float* W1_all    = (const float*)d_in[26];
    const float* b1_all    = (const float*)d_in[27];
    const float* W2_all    = (const float*)d_in[28];
    const float* b2_all    = (const float*)d_in[29];
    const float* ln_g      = (const float*)d_in[30];
    const float* ln_b      = (const float*)d_in[31];

    float* logits = (float*)d_out;
    float* kout = logits + (long)Bc * Tc * Vc;
    float* vout = kout + (long)Lc * Bc * NCc * Dc;

    static cudaStream_t s2 = nullptr;
    static cudaEvent_t evFork, evWo, evXat, evMlp, evEmb;
    if (!s2) {
        cudaStreamCreateWithFlags(&s2, cudaStreamNonBlocking);
        cudaEventCreateWithFlags(&evFork, cudaEventDisableTiming);
        cudaEventCreateWithFlags(&evWo,   cudaEventDisableTiming);
        cudaEventCreateWithFlags(&evXat,  cudaEventDisableTiming);
        cudaEventCreateWithFlags(&evMlp,  cudaEventDisableTiming);
        cudaEventCreateWithFlags(&evEmb,  cudaEventDisableTiming);
        cudaFuncSetAttribute(flash_kernel<1>, cudaFuncAttributeMaxDynamicSharedMemorySize, FLASH_SMEM);
        cudaFuncSetAttribute(flashp_kernel,   cudaFuncAttributeMaxDynamicSharedMemorySize, FLASH_SMEM);
    }

    __half *wqkv_h, *wqkv_l, *wo_h, *wo_l, *xwq_h, *xwq_l, *xwo_h, *xwo_l;
    __half *w1_h, *w1_l, *w2_h, *w2_l, *emb_h, *emb_l;
    __half *ck_h, *ck_l, *cv_h, *cv_l;
    float *gx, *pO, *pm, *pl;
    __half *hf, *atf, *hidf, *qf, *kh, *kl, *vh, *vl;
    SYM(wqkv_h, s_Wqkv_h); SYM(wqkv_l, s_Wqkv_l);
    SYM(wo_h, s_Wo_h);  SYM(wo_l, s_Wo_l);
    SYM(xwq_h, s_xWq_h); SYM(xwq_l, s_xWq_l);
    SYM(xwo_h, s_xWo_h); SYM(xwo_l, s_xWo_l);
    SYM(w1_h, s_W1_h);  SYM(w1_l, s_W1_l);
    SYM(w2_h, s_W2_h);  SYM(w2_l, s_W2_l);
    SYM(emb_h, s_emb_h); SYM(emb_l, s_emb_l);
    SYM(ck_h, s_ck_h);  SYM(ck_l, s_ck_l);
    SYM(cv_h, s_cv_h);  SYM(cv_l, s_cv_l);
    SYM(gx, g_x);
    SYM(pO, p_O); SYM(pm, p_m); SYM(pl, p_l);
    SYM(hf, a_hf); SYM(atf, a_atf); SYM(hidf, a_hidf);
    SYM(qf, a_qf);
    SYM(kh, a_k_h); SYM(kl, a_k_l);
    SYM(vh, a_v_h); SYM(vl, a_v_l);

    const long XKV = (long)Bc * CTc * Dc;
    const long LBD = (long)Bc * NCc * Dc;
    const long WQKV = (long)Dc * D3;

    // ---- fork side stream; one-time splits on s2 ----
    cudaEventRecord(evFork, 0);
    cudaStreamWaitEvent(s2, evFork, 0);

    split_fp16(s2, Wo_all,  wo_h,  wo_l,  (long)Lc * DDm);
    cudaEventRecord(evWo, s2);
    split_fp16(s2, xWq_all, xwq_h, xwq_l, (long)Lc * DDm);
    split_fp16(s2, cross_k, ck_h,  ck_l,  (long)Lc * Bc * CTc * Dc);
    split_fp16(s2, cross_v, cv_h,  cv_l,  (long)Lc * Bc * CTc * Dc);
    split_fp16(s2, xWo_all, xwo_h, xwo_l, (long)Lc * DDm);
    cudaEventRecord(evXat, s2);
    split_fp16(s2, W1_all,  w1_h,  w1_l,  (long)Lc * Dc * D4);
    split_fp16(s2, W2_all,  w2_h,  w2_l,  (long)Lc * Dc * D4);
    cudaEventRecord(evMlp, s2);
    split_fp16(s2, tokemb,  emb_h, emb_l, (long)Vc * Dc);
    cudaEventRecord(evEmb, s2);

    // ---- main stream ----
    {
        long n4 = (long)Lc * Dc * 192;
        dim3 grid((unsigned)((n4 + 255) / 256), 3);
        split_qkv3h_kernel<<<grid, 256>>>((const float4*)Wq_all, (const float4*)Wk_all,
                                          (const float4*)Wv_all,
                                          (__half2*)wqkv_h, (__half2*)wqkv_l, n4);
    }
    embed_kernel<<<Mrows, 256>>>(tokens, tokemb, posemb, gx);

    for (int l = 0; l < Lc; l++) {
        float* klayer = kout + l * LBD;
        float* vlayer = vout + l * LBD;

        // ---- self attention ----
        ln_half_kernel<<<Mrows, 256>>>(gx, hf, attn_ln_g + l * Dc, attn_ln_b + l * Dc);
        gemm_qkv_h2<<<dim3(Mrows/64, D3/64), 128>>>(hf,
                                                    wqkv_h + l * WQKV, wqkv_l + l * WQKV,
                                                    bq_all + l * Dc, bv_all + l * Dc,
                                                    qf, kh, kl, vh, vl, klayer, vlayer);
        flash_kernel<1><<<dim3(1, Tc/64, Bc*Hc), 128, FLASH_SMEM>>>(qf, kh, kl, vh, vl,
                                                                    atf, Tc, Tc);
        if (l == 0) cudaStreamWaitEvent(0, evWo, 0);
        gh2_sm(atf, wo_h + (long)l*DDm, wo_l + (long)l*DDm, gx, nullptr,
               bo_all + l*Dc, Mrows, Dc, Dc, Dc, Dc, Dc, 2);

        // ---- cross attention (split-K flash) ----
        ln_half_kernel<<<Mrows, 256>>>(gx, hf, xln_g + l * Dc, xln_b + l * Dc);
        if (l == 0) cudaStreamWaitEvent(0, evXat, 0);
        gh2_sm(hf, xwq_h + (long)l*DDm, xwq_l + (long)l*DDm, nullptr, qf,
               xbq_all + l*Dc, Mrows, Dc, Dc, Dc, Dc, Dc, 1);
        flashp_kernel<<<dim3(XSPL, Tc/64, Bc*Hc), 128, FLASH_SMEM>>>(qf,
                                                                     ck_h + l*XKV, ck_l + l*XKV,
                                                                     cv_h + l*XKV, cv_l + l*XKV,
                                                                     pO, pm, pl, CTc);
        flashc_kernel<<<dim3(Tc, Bc*Hc), HD>>>(pO, pm, pl, atf);
        gh2_sm(atf, xwo_h + (long)l*DDm, xwo_l + (long)l*DDm, gx, nullptr,
               xbo_all + l*Dc, Mrows, Dc, Dc, Dc, Dc, Dc, 2);

        // ---- MLP ----
        ln_half_kernel<<<Mrows, 256>>>(gx, hf, mln_g + l * Dc, mln_b + l * Dc);
        if (l == 0) cudaStreamWaitEvent(0, evMlp, 0);
        gh2(hf, w1_h + (long)l*Dc*D4, w1_l + (long)l*Dc*D4, nullptr, hidf,
            b1_all + (long)l*D4, Mrows, D4, Dc, Dc, D4, D4, 3);
        gh2_sm(hidf, w2_h + (long)l*Dc*D4, w2_l + (long)l*Dc*D4, gx, nullptr,
               b2_all + l*Dc, Mrows, Dc, D4, D4, Dc, Dc, 2);
    }

    // final LN (fp16) + fp16 2-term logits GEMM
    ln_half_kernel<<<Mrows, 256>>>(gx, hf, ln_g, ln_b);
    cudaStreamWaitEvent(0, evEmb, 0);
    {
        dim3 grid(Mrows / 64, (Vc + 63) / 64);
        gemm_f16_logits<<<grid, 128>>>(hf, emb_h, emb_l, logits,
                                       Mrows, Vc, Dc, Dc, Dc, Vc);
    }

    (void)in_sizes; (void)n_in; (void)out_size;
}

// round 17
// speedup vs baseline: 1.3350x; 1.0570x over previous
#include <cuda_runtime.h>
#include <cuda_bf16.h>
#include <cuda_fp16.h>
#include <math.h>
#include <stdint.h>

// Problem constants
#define Lc 12
#define Bc 2
#define Tc 448
#define Dc 768
#define Hc 12
#define Vc 51865
#define NCc 448
#define CTc 1500
#define HD 64
#define Mrows (Bc*Tc)      // 896
#define DDm (Dc*Dc)
#define D4 (4*Dc)          // 3072
#define D3 (3*Dc)          // 2304
#define XSPL 4
#define XTPS 6

typedef __nv_bfloat16 bf16;

// -------------------- scratch (static device globals) -----------------------
__device__ __half s_Wqkv_h[(long)Lc*Dc*D3], s_Wqkv_l[(long)Lc*Dc*D3];
__device__ __half s_Wo_h[Lc*DDm],  s_Wo_l[Lc*DDm];
__device__ __half s_xWq_h[Lc*DDm], s_xWq_l[Lc*DDm];
__device__ __half s_xWo_h[Lc*DDm], s_xWo_l[Lc*DDm];
__device__ __half s_W1f[(long)Lc*Dc*D4];           // W1 single fp16
__device__ __half s_W2f[(long)Lc*Dc*D4];           // W2 single fp16
__device__ __half s_emb_h[(long)Vc*Dc], s_emb_l[(long)Vc*Dc];
__device__ __half s_ck_h[(long)Lc*Bc*CTc*Dc], s_ck_l[(long)Lc*Bc*CTc*Dc];
__device__ __half s_cv_h[(long)Lc*Bc*CTc*Dc], s_cv_l[(long)Lc*Bc*CTc*Dc];
// activations
__device__ float g_x[Mrows*Dc];
__device__ __half a_hf[Mrows*Dc];
__device__ __half a_atf[Mrows*Dc];
__device__ __half a_hidf[Mrows*D4];
__device__ __half a_qf[Mrows*Dc];
__device__ __half a_k_h[Mrows*Dc], a_k_l[Mrows*Dc];
__device__ __half a_v_h[Mrows*Dc], a_v_l[Mrows*Dc];
// split-K flash partials
__device__ float p_O[(long)XSPL * Bc*Hc * Tc * HD];
__device__ float p_m[XSPL * Bc*Hc * Tc];
__device__ float p_l[XSPL * Bc*Hc * Tc];

// -------------------- small helpers ----------------------------------------
__device__ __forceinline__ void cpa16(void* dst, const void* src, int bytes) {
    uint32_t d = (uint32_t)__cvta_generic_to_shared(dst);
    asm volatile("cp.async.cg.shared.global [%0], [%1], 16, %2;\n"
                 :: "r"(d), "l"(src), "r"(bytes));
}
__device__ __forceinline__ void cp_commit() { asm volatile("cp.async.commit_group;\n"); }
__device__ __forceinline__ void cp_wait0()  { asm volatile("cp.async.wait_group 0;\n"); }
__device__ __forceinline__ void cp_wait1()  { asm volatile("cp.async.wait_group 1;\n"); }

__device__ __forceinline__ void ldm4(uint32_t* r, const void* p) {
    uint32_t a = (uint32_t)__cvta_generic_to_shared(p);
    asm volatile("ldmatrix.sync.aligned.m8n8.x4.shared.b16 {%0,%1,%2,%3}, [%4];"
                 : "=r"(r[0]), "=r"(r[1]), "=r"(r[2]), "=r"(r[3]) : "r"(a));
}
__device__ __forceinline__ void ldm4t(uint32_t* r, const void* p) {
    uint32_t a = (uint32_t)__cvta_generic_to_shared(p);
    asm volatile("ldmatrix.sync.aligned.m8n8.x4.trans.shared.b16 {%0,%1,%2,%3}, [%4];"
                 : "=r"(r[0]), "=r"(r[1]), "=r"(r[2]), "=r"(r[3]) : "r"(a));
}
__device__ __forceinline__ void mma16816h(float* d, const uint32_t* a, const uint32_t* b) {
    asm volatile("mma.sync.aligned.m16n8k16.row.col.f32.f16.f16.f32 "
                 "{%0,%1,%2,%3}, {%4,%5,%6,%7}, {%8,%9}, {%0,%1,%2,%3};"
                 : "+f"(d[0]), "+f"(d[1]), "+f"(d[2]), "+f"(d[3])
                 : "r"(a[0]), "r"(a[1]), "r"(a[2]), "r"(a[3]), "r"(b[0]), "r"(b[1]));
}
__device__ __forceinline__ uint32_t packh(float x, float y) {
    __half2 h = __floats2half2_rn(x, y);
    return *(uint32_t*)&h;
}

// -------------------- conversions -------------------------------------------
__global__ void split4h_kernel(const float4* __restrict__ src,
                               __half2* __restrict__ h2,
                               __half2* __restrict__ l2, long n4) {
    long i = (long)blockIdx.x * blockDim.x + threadIdx.x;
    if (i >= n4) return;
    float4 v = src[i];
    __half h0 = __float2half(v.x), h1 = __float2half(v.y);
    __half h2v = __float2half(v.z), h3 = __float2half(v.w);
    h2[2*i]   = __half2(h0, h1);
    h2[2*i+1] = __half2(h2v, h3);
    l2[2*i]   = __half2(__float2half(v.x - __half2float(h0)),
                        __float2half(v.y - __half2float(h1)));
    l2[2*i+1] = __half2(__float2half(v.z - __half2float(h2v)),
                        __float2half(v.w - __half2float(h3)));
}

__global__ void cvt4h_kernel(const float4* __restrict__ src,
                             __half2* __restrict__ dst, long n4) {
    long i = (long)blockIdx.x * blockDim.x + threadIdx.x;
    if (i >= n4) return;
    float4 v = src[i];
    dst[2*i]   = __floats2half2_rn(v.x, v.y);
    dst[2*i+1] = __floats2half2_rn(v.z, v.w);
}

// merged strided fp16 split: Wq,Wk,Wv -> [L][768][2304] hi/lo
__global__ void split_qkv3h_kernel(const float4* __restrict__ sq,
                                   const float4* __restrict__ sk,
                                   const float4* __restrict__ sv,
                                   __half2* __restrict__ h2,
                                   __half2* __restrict__ l2, long n4) {
    long i = (long)blockIdx.x * blockDim.x + threadIdx.x;
    if (i >= n4) return;
    const float4* src = (blockIdx.y == 0) ? sq : (blockIdx.y == 1) ? sk : sv;
    int dstoff4 = blockIdx.y * 192;
    long row = i / 192;
    int c4 = (int)(i - row * 192);
    long d4 = row * 576 + dstoff4 + c4;
    float4 v = src[i];
    __half h0 = __float2half(v.x), h1 = __float2half(v.y);
    __half h2v = __float2half(v.z), h3 = __float2half(v.w);
    h2[2*d4]   = __half2(h0, h1);
    h2[2*d4+1] = __half2(h2v, h3);
    l2[2*d4]   = __half2(__float2half(v.x - __half2float(h0)),
                         __float2half(v.y - __half2float(h1)));
    l2[2*d4+1] = __half2(__float2half(v.z - __half2float(h2v)),
                         __float2half(v.w - __half2float(h3)));
}

// -------------------- reductions --------------------------------------------
__device__ __forceinline__ float blk_sum(float v) {
    __shared__ float s[32];
    int lane = threadIdx.x & 31, warp = threadIdx.x >> 5;
    #pragma unroll
    for (int o = 16; o > 0; o >>= 1) v += __shfl_down_sync(0xffffffffu, v, o);
    if (lane == 0) s[warp] = v;
    __syncthreads();
    int nw = blockDim.x >> 5;
    v = (threadIdx.x < nw) ? s[threadIdx.x] : 0.f;
    if (warp == 0) {
        #pragma unroll
        for (int o = 16; o > 0; o >>= 1) v += __shfl_down_sync(0xffffffffu, v, o);
        if (lane == 0) s[0] = v;
    }
    __syncthreads();
    float r = s[0];
    __syncthreads();
    return r;
}

// -------------------- embed / ln --------------------------------------------
__global__ void embed_kernel(const int* __restrict__ tokens,
                             const float* __restrict__ tokemb,
                             const float* __restrict__ pos,
                             float* __restrict__ x) {
    int row = blockIdx.x;
    int t = row % Tc;
    int tok = tokens[row];
    const float* te = tokemb + (long)tok * Dc;
    const float* pe = pos + (long)t * Dc;
    float* out = x + (long)row * Dc;
    for (int d = threadIdx.x; d < Dc; d += blockDim.x)
        out[d] = te[d] + pe[d];
}

__global__ void ln_half_kernel(const float* __restrict__ x,
                               __half* __restrict__ oh,
                               const float* __restrict__ g, const float* __restrict__ b) {
    const float* row = x + (long)blockIdx.x * Dc;
    long base = (long)blockIdx.x * Dc;
    int tid = threadIdx.x;
    float v0 = row[tid], v1 = row[tid + 256], v2 = row[tid + 512];
    float s  = blk_sum(v0 + v1 + v2);
    float s2 = blk_sum(v0*v0 + v1*v1 + v2*v2);
    float mean = s * (1.f / (float)Dc);
    float var = s2 * (1.f / (float)Dc) - mean * mean;
    float inv = rsqrtf(var + 1e-5f);
    #pragma unroll
    for (int j = 0; j < 3; j++) {
        int d = tid + j * 256;
        float v = (j == 0) ? v0 : (j == 1) ? v1 : v2;
        oh[base + d] = __float2half((v - mean) * inv * g[d] + b[d]);
    }
}

// -------------------- flash (fp16 2-term; Q/P single, K/V hi/lo) -------------
template<int CAUSAL>
__global__ __launch_bounds__(128)
void flash_kernel(const __half* __restrict__ Q,
                  const __half* __restrict__ Kh, const __half* __restrict__ Kl,
                  const __half* __restrict__ Vh, const __half* __restrict__ Vl,
                  __half* __restrict__ O,
                  int kvlen, int kvrows) {
    constexpr int LDK = HD + 8;
    __shared__ __half sK[2][64 * LDK];
    __shared__ __half sV[2][64 * LDK];

    int z = blockIdx.z;
    int b = z / Hc, h = z - b * Hc;
    int qt = blockIdx.y;
    int q0 = qt * 64;
    long qoff = (long)b * Tc * Dc + h * HD;
    long koff = (long)b * kvrows * Dc + h * HD;
    Q += qoff; O += qoff;
    Kh += koff; Kl += koff; Vh += koff; Vl += koff;

    int tid = threadIdx.x, lane = tid & 31, warp = tid >> 5;

    #pragma unroll
    for (int i = 0; i < 4; i++) {
        int idx = i * 128 + tid;
        int row = idx >> 3, c = (idx & 7) * 8;
        cpa16(&sK[0][row * LDK + c], Q + (long)(q0 + row) * Dc + c, 16);
    }
    cp_commit(); cp_wait0();
    __syncthreads();
    uint32_t qf[4][4];
    #pragma unroll
    for (int kc = 0; kc < 4; kc++)
        ldm4(qf[kc], &sK[0][(warp*16 + (lane & 15)) * LDK + kc*16 + (lane >> 4) * 8]);
    __syncthreads();

    float m0 = -1e30f, m1 = -1e30f, l0 = 0.f, l1 = 0.f;
    float oacc[8][4] = {};

    int ntile = CAUSAL ? (qt + 1) : ((kvlen + 63) >> 6);
    int qrow0 = q0 + warp*16 + (lane >> 2);
    int qrow1 = qrow0 + 8;

    for (int j = 0; j < ntile; j++) {
        int k0 = j * 64;
        #pragma unroll
        for (int i = 0; i < 4; i++) {
            int idx = i * 128 + tid;
            int row = idx >> 3, c = (idx & 7) * 8;
            int inb = (k0 + row < kvlen);
            int bytes = inb ? 16 : 0;
            long off = inb ? ((long)(k0 + row) * Dc + c) : 0;
            cpa16(&sK[0][row * LDK + c], Kh + off, bytes);
            cpa16(&sK[1][row * LDK + c], Kl + off, bytes);
            cpa16(&sV[0][row * LDK + c], Vh + off, bytes);
            cpa16(&sV[1][row * LDK + c], Vl + off, bytes);
        }
        cp_commit(); cp_wait0();
        __syncthreads();

        float s[8][4] = {};
        #pragma unroll
        for (int kc = 0; kc < 4; kc++) {
            uint32_t bh[8][2], bl[8][2];
            #pragma unroll
            for (int nf2 = 0; nf2 < 4; nf2++) {
                uint32_t r[4];
                ldm4(r, &sK[0][(nf2*16 + (lane & 15)) * LDK + kc*16 + (lane >> 4) * 8]);
                bh[2*nf2][0] = r[0]; bh[2*nf2+1][0] = r[1];
                bh[2*nf2][1] = r[2]; bh[2*nf2+1][1] = r[3];
                ldm4(r, &sK[1][(nf2*16 + (lane & 15)) * LDK + kc*16 + (lane >> 4) * 8]);
                bl[2*nf2][0] = r[0]; bl[2*nf2+1][0] = r[1];
                bl[2*nf2][1] = r[2]; bl[2*nf2+1][1] = r[3];
            }
            #pragma unroll
            for (int nf = 0; nf < 8; nf++) {
                mma16816h(s[nf], qf[kc], bh[nf]);
                mma16816h(s[nf], qf[kc], bl[nf]);
            }
        }

        #pragma unroll
        for (int nf = 0; nf < 8; nf++) {
            #pragma unroll
            for (int e = 0; e < 4; e++) {
                int col = k0 + nf*8 + (lane & 3)*2 + (e & 1);
                int qr = (e < 2) ? qrow0 : qrow1;
                bool ok = (col < kvlen) && (!CAUSAL || col <= qr);
                s[nf][e] = ok ? (s[nf][e] * 0.125f) : -1e30f;
            }
        }

        float rm0 = -1e30f, rm1 = -1e30f;
        #pragma unroll
        for (int nf = 0; nf < 8; nf++) {
            rm0 = fmaxf(rm0, fmaxf(s[nf][0], s[nf][1]));
            rm1 = fmaxf(rm1, fmaxf(s[nf][2], s[nf][3]));
        }
        rm0 = fmaxf(rm0, __shfl_xor_sync(0xffffffffu, rm0, 1));
        rm0 = fmaxf(rm0, __shfl_xor_sync(0xffffffffu, rm0, 2));
        rm1 = fmaxf(rm1, __shfl_xor_sync(0xffffffffu, rm1, 1));
        rm1 = fmaxf(rm1, __shfl_xor_sync(0xffffffffu, rm1, 2));
        float mn0 = fmaxf(m0, rm0), mn1 = fmaxf(m1, rm1);
        float f0 = __expf(m0 - mn0), f1 = __expf(m1 - mn1);
        float rs0 = 0.f, rs1 = 0.f;
        #pragma unroll
        for (int nf = 0; nf < 8; nf++) {
            float p0 = __expf(s[nf][0] - mn0);
            float p1 = __expf(s[nf][1] - mn0);
            float p2 = __expf(s[nf][2] - mn1);
            float p3 = __expf(s[nf][3] - mn1);
            s[nf][0] = p0; s[nf][1] = p1; s[nf][2] = p2; s[nf][3] = p3;
            rs0 += p0 + p1;
            rs1 += p2 + p3;
        }
        rs0 += __shfl_xor_sync(0xffffffffu, rs0, 1);
        rs0 += __shfl_xor_sync(0xffffffffu, rs0, 2);
        rs1 += __shfl_xor_sync(0xffffffffu, rs1, 1);
        rs1 += __shfl_xor_sync(0xffffffffu, rs1, 2);
        l0 = l0 * f0 + rs0;
        l1 = l1 * f1 + rs1;
        m0 = mn0; m1 = mn1;
        #pragma unroll
        for (int nf = 0; nf < 8; nf++) {
            oacc[nf][0] *= f0; oacc[nf][1] *= f0;
            oacc[nf][2] *= f1; oacc[nf][3] *= f1;
        }

        uint32_t pa[4][4];
        #pragma unroll
        for (int kc = 0; kc < 4; kc++) {
            pa[kc][0] = packh(s[2*kc][0],   s[2*kc][1]);
            pa[kc][1] = packh(s[2*kc][2],   s[2*kc][3]);
            pa[kc][2] = packh(s[2*kc+1][0], s[2*kc+1][1]);
            pa[kc][3] = packh(s[2*kc+1][2], s[2*kc+1][3]);
        }

        #pragma unroll
        for (int kk = 0; kk < 4; kk++) {
            uint32_t vfh[8][2], vfl[8][2];
            #pragma unroll
            for (int nf2 = 0; nf2 < 4; nf2++) {
                uint32_t r[4];
                ldm4t(r, &sV[0][(kk*16 + (lane & 15)) * LDK + nf2*16 + (lane >> 4) * 8]);
                vfh[2*nf2][0] = r[0]; vfh[2*nf2][1] = r[1];
                vfh[2*nf2+1][0] = r[2]; vfh[2*nf2+1][1] = r[3];
                ldm4t(r, &sV[1][(kk*16 + (lane & 15)) * LDK + nf2*16 + (lane >> 4) * 8]);
                vfl[2*nf2][0] = r[0]; vfl[2*nf2][1] = r[1];
                vfl[2*nf2+1][0] = r[2]; vfl[2*nf2+1][1] = r[3];
            }
            #pragma unroll
            for (int nf = 0; nf < 8; nf++) {
                mma16816h(oacc[nf], pa[kk], vfh[nf]);
                mma16816h(oacc[nf], pa[kk], vfl[nf]);
            }
        }
        __syncthreads();
    }

    float il0 = 1.f / l0, il1 = 1.f / l1;
    #pragma unroll
    for (int nf = 0; nf < 8; nf++) {
        int col = nf*8 + (lane & 3)*2;
        *(__half2*)&O[(long)qrow0 * Dc + col] =
            __floats2half2_rn(oacc[nf][0] * il0, oacc[nf][1] * il0);
        *(__half2*)&O[(long)qrow1 * Dc + col] =
            __floats2half2_rn(oacc[nf][2] * il1, oacc[nf][3] * il1);
    }
}

// -------------------- split-K flash (fp16 2-term, partials) ------------------
__global__ __launch_bounds__(128)
void flashp_kernel(const __half* __restrict__ Q,
                   const __half* __restrict__ Kh, const __half* __restrict__ Kl,
                   const __half* __restrict__ Vh, const __half* __restrict__ Vl,
                   float* __restrict__ pO, float* __restrict__ pm,
                   float* __restrict__ pl, int kvlen) {
    constexpr int LDK = HD + 8;
    __shared__ __half sK[2][64 * LDK];
    __shared__ __half sV[2][64 * LDK];

    int sp = blockIdx.x;
    int z = blockIdx.z;
    int b = z / Hc, h = z - b * Hc;
    int qt = blockIdx.y;
    int q0 = qt * 64;
    long qoff = (long)b * Tc * Dc + h * HD;
    long koff = (long)b * CTc * Dc + h * HD;
    Q += qoff;
    Kh += koff; Kl += koff; Vh += koff; Vl += koff;

    int tid = threadIdx.x, lane = tid & 31, warp = tid >> 5;

    #pragma unroll
    for (int i = 0; i < 4; i++) {
        int idx = i * 128 + tid;
        int row = idx >> 3, c = (idx & 7) * 8;
        cpa16(&sK[0][row * LDK + c], Q + (long)(q0 + row) * Dc + c, 16);
    }
    cp_commit(); cp_wait0();
    __syncthreads();
    uint32_t qf[4][4];
    #pragma unroll
    for (int kc = 0; kc < 4; kc++)
        ldm4(qf[kc], &sK[0][(warp*16 + (lane & 15)) * LDK + kc*16 + (lane >> 4) * 8]);
    __syncthreads();

    float m0 = -1e30f, m1 = -1e30f, l0 = 0.f, l1 = 0.f;
    float oacc[8][4] = {};

    int jlo = sp * XTPS, jhi = jlo + XTPS;
    int qrow0 = q0 + warp*16 + (lane >> 2);
    int qrow1 = qrow0 + 8;

    for (int j = jlo; j < jhi; j++) {
        int k0 = j * 64;
        #pragma unroll
        for (int i = 0; i < 4; i++) {
            int idx = i * 128 + tid;
            int row = idx >> 3, c = (idx & 7) * 8;
            int inb = (k0 + row < kvlen);
            int bytes = inb ? 16 : 0;
            long off = inb ? ((long)(k0 + row) * Dc + c) : 0;
            cpa16(&sK[0][row * LDK + c], Kh + off, bytes);
            cpa16(&sK[1][row * LDK + c], Kl + off, bytes);
            cpa16(&sV[0][row * LDK + c], Vh + off, bytes);
            cpa16(&sV[1][row * LDK + c], Vl + off, bytes);
        }
        cp_commit(); cp_wait0();
        __syncthreads();

        float s[8][4] = {};
        #pragma unroll
        for (int kc = 0; kc < 4; kc++) {
            uint32_t bh[8][2], bl[8][2];
            #pragma unroll
            for (int nf2 = 0; nf2 < 4; nf2++) {
                uint32_t r[4];
                ldm4(r, &sK[0][(nf2*16 + (lane & 15)) * LDK + kc*16 + (lane >> 4) * 8]);
                bh[2*nf2][0] = r[0]; bh[2*nf2+1][0] = r[1];
                bh[2*nf2][1] = r[2]; bh[2*nf2+1][1] = r[3];
                ldm4(r, &sK[1][(nf2*16 + (lane & 15)) * LDK + kc*16 + (lane >> 4) * 8]);
                bl[2*nf2][0] = r[0]; bl[2*nf2+1][0] = r[1];
                bl[2*nf2][1] = r[2]; bl[2*nf2+1][1] = r[3];
            }
            #pragma unroll
            for (int nf = 0; nf < 8; nf++) {
                mma16816h(s[nf], qf[kc], bh[nf]);
                mma16816h(s[nf], qf[kc], bl[nf]);
            }
        }

        #pragma unroll
        for (int nf = 0; nf < 8; nf++) {
            #pragma unroll
            for (int e = 0; e < 4; e++) {
                int col = k0 + nf*8 + (lane & 3)*2 + (e & 1);
                s[nf][e] = (col < kvlen) ? (s[nf][e] * 0.125f) : -1e30f;
            }
        }

        float rm0 = -1e30f, rm1 = -1e30f;
        #pragma unroll
        for (int nf = 0; nf < 8; nf++) {
            rm0 = fmaxf(rm0, fmaxf(s[nf][0], s[nf][1]));
            rm1 = fmaxf(rm1, fmaxf(s[nf][2], s[nf][3]));
        }
        rm0 = fmaxf(rm0, __shfl_xor_sync(0xffffffffu, rm0, 1));
        rm0 = fmaxf(rm0, __shfl_xor_sync(0xffffffffu, rm0, 2));
        rm1 = fmaxf(rm1, __shfl_xor_sync(0xffffffffu, rm1, 1));
        rm1 = fmaxf(rm1, __shfl_xor_sync(0xffffffffu, rm1, 2));
        float mn0 = fmaxf(m0, rm0), mn1 = fmaxf(m1, rm1);
        float f0 = __expf(m0 - mn0), f1 = __expf(m1 - mn1);
        float rs0 = 0.f, rs1 = 0.f;
        #pragma unroll
        for (int nf = 0; nf < 8; nf++) {
            float p0 = __expf(s[nf][0] - mn0);
            float p1 = __expf(s[nf][1] - mn0);
            float p2 = __expf(s[nf][2] - mn1);
            float p3 = __expf(s[nf][3] - mn1);
            s[nf][0] = p0; s[nf][1] = p1; s[nf][2] = p2; s[nf][3] = p3;
            rs0 += p0 + p1;
            rs1 += p2 + p3;
        }
        rs0 += __shfl_xor_sync(0xffffffffu, rs0, 1);
        rs0 += __shfl_xor_sync(0xffffffffu, rs0, 2);
        rs1 += __shfl_xor_sync(0xffffffffu, rs1, 1);
        rs1 += __shfl_xor_sync(0xffffffffu, rs1, 2);
        l0 = l0 * f0 + rs0;
        l1 = l1 * f1 + rs1;
        m0 = mn0; m1 = mn1;
        #pragma unroll
        for (int nf = 0; nf < 8; nf++) {
            oacc[nf][0] *= f0; oacc[nf][1] *= f0;
            oacc[nf][2] *= f1; oacc[nf][3] *= f1;
        }

        uint32_t pa[4][4];
        #pragma unroll
        for (int kc = 0; kc < 4; kc++) {
            pa[kc][0] = packh(s[2*kc][0],   s[2*kc][1]);
            pa[kc][1] = packh(s[2*kc][2],   s[2*kc][3]);
            pa[kc][2] = packh(s[2*kc+1][0], s[2*kc+1][1]);
            pa[kc][3] = packh(s[2*kc+1][2], s[2*kc+1][3]);
        }

        #pragma unroll
        for (int kk = 0; kk < 4; kk++) {
            uint32_t vfh[8][2], vfl[8][2];
            #pragma unroll
            for (int nf2 = 0; nf2 < 4; nf2++) {
                uint32_t r[4];
                ldm4t(r, &sV[0][(kk*16 + (lane & 15)) * LDK + nf2*16 + (lane >> 4) * 8]);
                vfh[2*nf2][0] = r[0]; vfh[2*nf2][1] = r[1];
                vfh[2*nf2+1][0] = r[2]; vfh[2*nf2+1][1] = r[3];
                ldm4t(r, &sV[1][(kk*16 + (lane & 15)) * LDK + nf2*16 + (lane >> 4) * 8]);
                vfl[2*nf2][0] = r[0]; vfl[2*nf2][1] = r[1];
                vfl[2*nf2+1][0] = r[2]; vfl[2*nf2+1][1] = r[3];
            }
            #pragma unroll
            for (int nf = 0; nf < 8; nf++) {
                mma16816h(oacc[nf], pa[kk], vfh[nf]);
                mma16816h(oacc[nf], pa[kk], vfl[nf]);
            }
        }
        __syncthreads();
    }

    long base = ((long)sp * (Bc*Hc) + z) * Tc;
    if ((lane & 3) == 0) {
        pm[base + qrow0] = m0; pl[base + qrow0] = l0;
        pm[base + qrow1] = m1; pl[base + qrow1] = l1;
    }
    #pragma unroll
    for (int nf = 0; nf < 8; nf++) {
        int col = nf*8 + (lane & 3)*2;
        float2* d0 = (float2*)&pO[(base + qrow0) * HD + col];
        float2* d1 = (float2*)&pO[(base + qrow1) * HD + col];
        *d0 = make_float2(oacc[nf][0], oacc[nf][1]);
        *d1 = make_float2(oacc[nf][2], oacc[nf][3]);
    }
}

__global__ void flashc_kernel(const float* __restrict__ pO,
                              const float* __restrict__ pm,
                              const float* __restrict__ pl,
                              __half* __restrict__ O) {
    int row = blockIdx.x, z = blockIdx.y, c = threadIdx.x;
    int b = z / Hc, h = z - b * Hc;
    float ms[XSPL];
    float mstar = -1e30f;
    #pragma unroll
    for (int s = 0; s < XSPL; s++) {
        ms[s] = pm[((long)s * (Bc*Hc) + z) * Tc + row];
        mstar = fmaxf(mstar, ms[s]);
    }
    float osum = 0.f, lsum = 0.f;
    #pragma unroll
    for (int s = 0; s < XSPL; s++) {
        long base = ((long)s * (Bc*Hc) + z) * Tc + row;
        float w = __expf(ms[s] - mstar);
        lsum += w * pl[base];
        osum += w * pO[base * HD + c];
    }
    long oi = (long)b * Tc * Dc + (long)row * Dc + h * HD + c;
    O[oi] = __float2half(osum / lsum);
}

// -------------------- fp16 TERMS-term GEMM (BM=64, TRANSB=0) ----------------
// modes: 0 Cf=acc; 1 out=acc+bias; 2 Cf+=acc+bias; 3 out=gelu(acc+bias)
template<int TERMS>
__global__ __launch_bounds__(128)
void gemm_h(const __half* __restrict__ A,
            const __half* __restrict__ Bh, const __half* __restrict__ Bl,
            float* Cf, __half* Chf,
            const float* __restrict__ bias,
            int M, int N, int K, int lda, int ldb, int ldc, int mode) {
    constexpr int BM = 64, BN = 64, BK = 32;
    constexpr int LDA = BK + 8, LDB = BN + 8;

    __shared__ __half sA[2][BM * LDA];
    __shared__ __half sB[2][TERMS][BK * LDB];

    int tid = threadIdx.x;
    int lane = tid & 31, warp = tid >> 5;
    int wm = warp >> 1, wn = warp & 1;
    int m0 = blockIdx.x * BM, n0 = blockIdx.y * BN;

    auto load_stage = [&](int s, int kt) {
        int k0 = kt * BK;
        #pragma unroll
        for (int i = 0; i < 2; i++) {
            int idx = i * 128 + tid;
            int row = idx >> 2, kc = (idx & 3) * 8;
            cpa16(&sA[s][row * LDA + kc], A + (long)(m0 + row) * lda + k0 + kc, 16);
        }
        #pragma unroll
        for (int i = 0; i < 2; i++) {
            int idx = i * 128 + tid;
            int krow = idx >> 3, nc = (idx & 7) * 8;
            long off = (long)(k0 + krow) * ldb + n0 + nc;
            cpa16(&sB[s][0][krow * LDB + nc], Bh + off, 16);
            if (TERMS == 2)
                cpa16(&sB[s][1][krow * LDB + nc], Bl + off, 16);
        }
    };

    float acc[2][4][4] = {};
    int KT = K / BK;

    load_stage(0, 0);
    cp_commit();

    for (int kt = 0; kt < KT; kt++) {
        int cur = kt & 1;
        bool more = (kt + 1 < KT);
        if (more) { load_stage(cur ^ 1, kt + 1); cp_commit(); }
        if (more) cp_wait1(); else cp_wait0();
        __syncthreads();

        #pragma unroll
        for (int kf = 0; kf < 2; kf++) {
            uint32_t ah[2][4];
            #pragma unroll
            for (int mf = 0; mf < 2; mf++)
                ldm4(ah[mf], &sA[cur][(wm*32 + mf*16 + (lane & 15)) * LDA + kf*16 + (lane >> 4) * 8]);
            uint32_t bh[4][2], bl[4][2];
            #pragma unroll
            for (int nf2 = 0; nf2 < 2; nf2++) {
                uint32_t r[4];
                ldm4t(r, &sB[cur][0][(kf*16 + (lane & 15)) * LDB + wn*32 + nf2*16 + (lane >> 4) * 8]);
                bh[2*nf2][0] = r[0]; bh[2*nf2][1] = r[1];
                bh[2*nf2+1][0] = r[2]; bh[2*nf2+1][1] = r[3];
                if (TERMS == 2) {
                    ldm4t(r, &sB[cur][1][(kf*16 + (lane & 15)) * LDB + wn*32 + nf2*16 + (lane >> 4) * 8]);
                    bl[2*nf2][0] = r[0]; bl[2*nf2][1] = r[1];
                    bl[2*nf2+1][0] = r[2]; bl[2*nf2+1][1] = r[3];
                }
            }
            #pragma unroll
            for (int mf = 0; mf < 2; mf++)
                #pragma unroll
                for (int nf = 0; nf < 4; nf++) {
                    mma16816h(acc[mf][nf], ah[mf], bh[nf]);
                    if (TERMS == 2)
                        mma16816h(acc[mf][nf], ah[mf], bl[nf]);
                }
        }
        __syncthreads();
    }

    int r = lane >> 2, c = (lane & 3) * 2;
    #pragma unroll
    for (int mf = 0; mf < 2; mf++) {
        #pragma unroll
        for (int i = 0; i < 2; i++) {
            int grow = m0 + wm*32 + mf*16 + r + i*8;
            #pragma unroll
            for (int nf = 0; nf < 4; nf++) {
                #pragma unroll
                for (int j = 0; j < 2; j++) {
                    int gcol = n0 + wn*32 + nf*8 + c + j;
                    float v = acc[mf][nf][i*2 + j];
                    long ci = (long)grow * ldc + gcol;
                    if (mode >= 1) v += bias[gcol];
                    if (mode == 2) v += Cf[ci];
                    if (mode == 3) v = 0.5f * v * (1.f + erff(v * 0.70710678118654752f));
                    if (Cf) Cf[ci] = v;
                    if (Chf) Chf[ci] = __float2half(v);
                }
            }
        }
    }
}

// -------------------- fp16 TERMS-term small-tile GEMM (BM=32) ---------------
template<int TERMS>
__global__ __launch_bounds__(128)
void gemm_h_sm(const __half* __restrict__ A,
               const __half* __restrict__ Bh, const __half* __restrict__ Bl,
               float* Cf, __half* Chf,
               const float* __restrict__ bias,
               int M, int N, int K, int lda, int ldb, int ldc, int mode) {
    constexpr int BM = 32, BN = 64, BK = 32;
    constexpr int LDA = BK + 8, LDB = BN + 8;

    __shared__ __half sA[2][BM * LDA];
    __shared__ __half sB[2][TERMS][BK * LDB];

    int tid = threadIdx.x;
    int lane = tid & 31, wn = tid >> 5;
    int m0 = blockIdx.x * BM, n0 = blockIdx.y * BN;

    auto load_stage = [&](int s, int kt) {
        int k0 = kt * BK;
        {
            int row = tid >> 2, kc = (tid & 3) * 8;
            cpa16(&sA[s][row * LDA + kc], A + (long)(m0 + row) * lda + k0 + kc, 16);
        }
        #pragma unroll
        for (int i = 0; i < 2; i++) {
            int idx = i * 128 + tid;
            int krow = idx >> 3, nc = (idx & 7) * 8;
            long off = (long)(k0 + krow) * ldb + n0 + nc;
            cpa16(&sB[s][0][krow * LDB + nc], Bh + off, 16);
            if (TERMS == 2)
                cpa16(&sB[s][1][krow * LDB + nc], Bl + off, 16);
        }
    };

    float acc[2][2][4] = {};
    int KT = K / BK;

    load_stage(0, 0);
    cp_commit();

    for (int kt = 0; kt < KT; kt++) {
        int cur = kt & 1;
        bool more = (kt + 1 < KT);
        if (more) { load_stage(cur ^ 1, kt + 1); cp_commit(); }
        if (more) cp_wait1(); else cp_wait0();
        __syncthreads();

        #pragma unroll
        for (int kf = 0; kf < 2; kf++) {
            uint32_t ah[2][4];
            #pragma unroll
            for (int mf = 0; mf < 2; mf++)
                ldm4(ah[mf], &sA[cur][(mf*16 + (lane & 15)) * LDA + kf*16 + (lane >> 4) * 8]);
            uint32_t bh[2][2], bl[2][2];
            {
                uint32_t r[4];
                ldm4t(r, &sB[cur][0][(kf*16 + (lane & 15)) * LDB + wn*16 + (lane >> 4) * 8]);
                bh[0][0] = r[0]; bh[0][1] = r[1];
                bh[1][0] = r[2]; bh[1][1] = r[3];
                if (TERMS == 2) {
                    ldm4t(r, &sB[cur][1][(kf*16 + (lane & 15)) * LDB + wn*16 + (lane >> 4) * 8]);
                    bl[0][0] = r[0]; bl[0][1] = r[1];
                    bl[1][0] = r[2]; bl[1][1] = r[3];
                }
            }
            #pragma unroll
            for (int mf = 0; mf < 2; mf++)
                #pragma unroll
                for (int nf = 0; nf < 2; nf++) {
                    mma16816h(acc[mf][nf], ah[mf], bh[nf]);
                    if (TERMS == 2)
                        mma16816h(acc[mf][nf], ah[mf], bl[nf]);
                }
        }
        __syncthreads();
    }

    int r = lane >> 2, c = (lane & 3) * 2;
    #pragma unroll
    for (int mf = 0; mf < 2; mf++) {
        #pragma unroll
        for (int i = 0; i < 2; i++) {
            int grow = m0 + mf*16 + r + i*8;
            #pragma unroll
            for (int nf = 0; nf < 2; nf++) {
                #pragma unroll
                for (int j = 0; j < 2; j++) {
                    int gcol = n0 + wn*16 + nf*8 + c + j;
                    float v = acc[mf][nf][i*2 + j];
                    long ci = (long)grow * ldc + gcol;
                    if (mode >= 1) v += bias[gcol];
                    if (mode == 2) v += Cf[ci];
                    if (mode == 3) v = 0.5f * v * (1.f + erff(v * 0.70710678118654752f));
                    if (Cf) Cf[ci] = v;
                    if (Chf) Chf[ci] = __float2half(v);
                }
            }
        }
    }
}

// -------------------- fp16 fused QKV GEMM ------------------------------------
// region 0: q -> single fp16; 1: k -> cache fp32 + fp16 hi/lo; 2: v likewise + bias
__global__ __launch_bounds__(128)
void gemm_qkv_h2(const __half* __restrict__ A,
                 const __half* __restrict__ Bh, const __half* __restrict__ Bl,
                 const float* __restrict__ bq, const float* __restrict__ bv,
                 __half* __restrict__ qf,
                 __half* __restrict__ kh, __half* __restrict__ kl,
                 __half* __restrict__ vh, __half* __restrict__ vl,
                 float* __restrict__ kcache, float* __restrict__ vcache) {
    constexpr int BM = 64, BN = 64, BK = 32;
    constexpr int LDA = BK + 8, LDB = BN + 8;
    const int K = Dc, ldb = D3, lda = Dc;

    __shared__ __half sA[2][BM * LDA];
    __shared__ __half sB[2][2][BK * LDB];

    int tid = threadIdx.x;
    int lane = tid & 31, warp = tid >> 5;
    int wm = warp >> 1, wn = warp & 1;
    int m0 = blockIdx.x * BM, n0 = blockIdx.y * BN;

    int reg = n0 / Dc;
    int cn0 = n0 - reg * Dc;
    const float* bias = (reg == 0) ? bq : (reg == 2 ? bv : nullptr);
    float* Cf = (reg == 1) ? kcache : (reg == 2 ? vcache : nullptr);
    __half* Ch = (reg == 1) ? kh : vh;
    __half* Cl = (reg == 1) ? kl : vl;

    auto load_stage = [&](int s, int kt) {
        int k0 = kt * BK;
        #pragma unroll
        for (int i = 0; i < 2; i++) {
            int idx = i * 128 + tid;
            int row = idx >> 2, kc = (idx & 3) * 8;
            cpa16(&sA[s][row * LDA + kc], A + (long)(m0 + row) * lda + k0 + kc, 16);
        }
        #pragma unroll
        for (int i = 0; i < 2; i++) {
            int idx = i * 128 + tid;
            int krow = idx >> 3, nc = (idx & 7) * 8;
            long off = (long)(k0 + krow) * ldb + n0 + nc;
            cpa16(&sB[s][0][krow * LDB + nc], Bh + off, 16);
            cpa16(&sB[s][1][krow * LDB + nc], Bl + off, 16);
        }
    };

    float acc[2][4][4] = {};
    int KT = K / BK;

    load_stage(0, 0);
    cp_commit();

    for (int kt = 0; kt < KT; kt++) {
        int cur = kt & 1;
        bool more = (kt + 1 < KT);
        if (more) { load_stage(cur ^ 1, kt + 1); cp_commit(); }
        if (more) cp_wait1(); else cp_wait0();
        __syncthreads();

        #pragma unroll
        for (int kf = 0; kf < 2; kf++) {
            uint32_t ah[2][4];
            #pragma unroll
            for (int mf = 0; mf < 2; mf++)
                ldm4(ah[mf], &sA[cur][(wm*32 + mf*16 + (lane & 15)) * LDA + kf*16 + (lane >> 4) * 8]);
            uint32_t bh[4][2], bl[4][2];
            #pragma unroll
            for (int nf2 = 0; nf2 < 2; nf2++) {
                uint32_t r[4];
                ldm4t(r, &sB[cur][0][(kf*16 + (lane & 15)) * LDB + wn*32 + nf2*16 + (lane >> 4) * 8]);
                bh[2*nf2][0] = r[0]; bh[2*nf2][1] = r[1];
                bh[2*nf2+1][0] = r[2]; bh[2*nf2+1][1] = r[3];
                ldm4t(r, &sB[cur][1][(kf*16 + (lane & 15)) * LDB + wn*32 + nf2*16 + (lane >> 4) * 8]);
                bl[2*nf2][0] = r[0]; bl[2*nf2][1] = r[1];
                bl[2*nf2+1][0] = r[2]; bl[2*nf2+1][1] = r[3];
            }
            #pragma unroll
            for (int mf = 0; mf < 2; mf++)
                #pragma unroll
                for (int nf = 0; nf < 4; nf++) {
                    mma16816h(acc[mf][nf], ah[mf], bh[nf]);
                    mma16816h(acc[mf][nf], ah[mf], bl[nf]);
                }
        }
        __syncthreads();
    }

    int r = lane >> 2, c = (lane & 3) * 2;
    #pragma unroll
    for (int mf = 0; mf < 2; mf++) {
        #pragma unroll
        for (int i = 0; i < 2; i++) {
            int grow = m0 + wm*32 + mf*16 + r + i*8;
            #pragma unroll
            for (int nf = 0; nf < 4; nf++) {
                #pragma unroll
                for (int j = 0; j < 2; j++) {
                    int col = cn0 + wn*32 + nf*8 + c + j;
                    float v = acc[mf][nf][i*2 + j];
                    if (bias) v += bias[col];
                    long ci = (long)grow * Dc + col;
                    if (reg == 0) {
                        qf[ci] = __float2half(v);
                    } else {
                        Cf[ci] = v;
                        __half h = __float2half(v);
                        Ch[ci] = h;
                        Cl[ci] = __float2half(v - __half2float(h));
                    }
                }
            }
        }
    }
}

// -------------------- fp16 2-term logits GEMM (TRANSB=1) ---------------------
__global__ __launch_bounds__(128)
void gemm_f16_logits(const __half* __restrict__ A,
                     const __half* __restrict__ Bh, const __half* __restrict__ Bl,
                     float* __restrict__ Cf,
                     int M, int N, int K, int lda, int ldb, int ldc) {
    constexpr int BM = 64, BN = 64, BK = 32;
    constexpr int LDA = BK + 8, LDB = BK + 8;

    __shared__ __half sA[2][BM * LDA];
    __shared__ __half sB[2][2][BN * LDB];

    int tid = threadIdx.x;
    int lane = tid & 31, warp = tid >> 5;
    int wm = warp >> 1, wn = warp & 1;
    int m0 = blockIdx.x * BM, n0 = blockIdx.y * BN;

    auto load_stage = [&](int s, int kt) {
        int k0 = kt * BK;
        #pragma unroll
        for (int i = 0; i < 2; i++) {
            int idx = i * 128 + tid;
            int row = idx >> 2, kc = (idx & 3) * 8;
            cpa16(&sA[s][row * LDA + kc], A + (long)(m0 + row) * lda + k0 + kc, 16);
        }
        #pragma unroll
        for (int i = 0; i < 2; i++) {
            int idx = i * 128 + tid;
            int nrow = idx >> 2, kc = (idx & 3) * 8;
            int gn = n0 + nrow;
            int bytes = (gn < N) ? 16 : 0;
            long off = (long)(gn < N ? gn : 0) * ldb + k0 + kc;
            cpa16(&sB[s][0][nrow * LDB + kc], Bh + off, bytes);
            cpa16(&sB[s][1][nrow * LDB + kc], Bl + off, bytes);
        }
    };

    float acc[2][4][4] = {};
    int KT = K / BK;

    load_stage(0, 0);
    cp_commit();

    for (int kt = 0; kt < KT; kt++) {
        int cur = kt & 1;
        bool more = (kt + 1 < KT);
        if (more) { load_stage(cur ^ 1, kt + 1); cp_commit(); }
        if (more) cp_wait1(); else cp_wait0();
        __syncthreads();

        #pragma unroll
        for (int kf = 0; kf < 2; kf++) {
            uint32_t ah[2][4];
            #pragma unroll
            for (int mf = 0; mf < 2; mf++)
                ldm4(ah[mf], &sA[cur][(wm*32 + mf*16 + (lane & 15)) * LDA + kf*16 + (lane >> 4) * 8]);
            uint32_t bh[4][2], bl[4][2];
            #pragma unroll
            for (int nf2 = 0; nf2 < 2; nf2++) {
                uint32_t r[4];
                ldm4(r, &sB[cur][0][(wn*32 + nf2*16 + (lane & 15)) * LDB + kf*16 + (lane >> 4) * 8]);
                bh[2*nf2][0] = r[0]; bh[2*nf2+1][0] = r[1];
                bh[2*nf2][1] = r[2]; bh[2*nf2+1][1] = r[3];
                ldm4(r, &sB[cur][1][(wn*32 + nf2*16 + (lane & 15)) * LDB + kf*16 + (lane >> 4) * 8]);
                bl[2*nf2][0] = r[0]; bl[2*nf2+1][0] = r[1];
                bl[2*nf2][1] = r[2]; bl[2*nf2+1][1] = r[3];
            }
            #pragma unroll
            for (int mf = 0; mf < 2; mf++)
                #pragma unroll
                for (int nf = 0; nf < 4; nf++) {
                    mma16816h(acc[mf][nf], ah[mf], bh[nf]);
                    mma16816h(acc[mf][nf], ah[mf], bl[nf]);
                }
        }
        __syncthreads();
    }

    int r = lane >> 2, c = (lane & 3) * 2;
    #pragma unroll
    for (int mf = 0; mf < 2; mf++) {
        #pragma unroll
        for (int i = 0; i < 2; i++) {
            int grow = m0 + wm*32 + mf*16 + r + i*8;
            #pragma unroll
            for (int nf = 0; nf < 4; nf++) {
                #pragma unroll
                for (int j = 0; j < 2; j++) {
                    int gcol = n0 + wn*32 + nf*8 + c + j;
                    if (gcol >= N) continue;
                    Cf[(long)grow * ldc + gcol] = acc[mf][nf][i*2 + j];
                }
            }
        }
    }
}

// -------------------- host helpers ------------------------------------------
static inline void split_fp16(cudaStream_t st, const float* src, __half* h, __half* l, long n) {
    long n4 = n / 4;
    int blocks = (int)((n4 + 255) / 256);
    split4h_kernel<<<blocks, 256, 0, st>>>((const float4*)src, (__half2*)h,
                                           (__half2*)l, n4);
}
static inline void cvt_fp16(cudaStream_t st, const float* src, __half* dst, long n) {
    long n4 = n / 4;
    int blocks = (int)((n4 + 255) / 256);
    cvt4h_kernel<<<blocks, 256, 0, st>>>((const float4*)src, (__half2*)dst, n4);
}
template<int TERMS>
static inline void gh(const __half* A, const __half* Bh, const __half* Bl,
                      float* Cf, __half* Chf, const float* bias,
                      int M, int N, int K, int lda, int ldb, int ldc, int mode) {
    dim3 grid(M / 64, N / 64);
    gemm_h<TERMS><<<grid, 128>>>(A, Bh, Bl, Cf, Chf, bias, M, N, K, lda, ldb, ldc, mode);
}
template<int TERMS>
static inline void gh_sm(const __half* A, const __half* Bh, const __half* Bl,
                         float* Cf, __half* Chf, const float* bias,
                         int M, int N, int K, int lda, int ldb, int ldc, int mode) {
    dim3 grid(M / 32, N / 64);
    gemm_h_sm<TERMS><<<grid, 128>>>(A, Bh, Bl, Cf, Chf, bias, M, N, K, lda, ldb, ldc, mode);
}

#define SYM(p, s) cudaGetSymbolAddress((void**)&p, s)

extern "C" void kernel_launch(void* const* d_in, const int* in_sizes, int n_in,
                              void* d_out, int out_size) {
    const int*   tokens    = (const int*)  d_in[0];
    const float* cross_k   = (const float*)d_in[3];
    const float* cross_v   = (const float*)d_in[4];
    const float* tokemb    = (const float*)d_in[6];
    const float* posemb    = (const float*)d_in[7];
    const float* attn_ln_g = (const float*)d_in[9];
    const float* attn_ln_b = (const float*)d_in[10];
    const float* Wq_all    = (const float*)d_in[11];
    const float* bq_all    = (const float*)d_in[12];
    const float* Wk_all    = (const float*)d_in[13];
    const float* Wv_all    = (const float*)d_in[14];
    const float* bv_all    = (const float*)d_in[15];
    const float* Wo_all    = (const float*)d_in[16];
    const float* bo_all    = (const float*)d_in[17];
    const float* xln_g     = (const float*)d_in[18];
    const float* xln_b     = (const float*)d_in[19];
    const float* xWq_all   = (const float*)d_in[20];
    const float* xbq_all   = (const float*)d_in[21];
    const float* xWo_all   = (const float*)d_in[22];
    const float* xbo_all   = (const float*)d_in[23];
    const float* mln_g     = (const float*)d_in[24];
    const float* mln_b     = (const float*)d_in[25];
    const float* W1_all    = (const float*)d_in[26];
    const float* b1_all    = (const float*)d_in[27];
    const float* W2_all    = (const float*)d_in[28];
    const float* b2_all    = (const float*)d_in[29];
    const float* ln_g      = (const float*)d_in[30];
    const float* ln_b      = (const float*)d_in[31];

    float* logits = (float*)d_out;
    float* kout = logits + (long)Bc * Tc * Vc;
    float* vout = kout + (long)Lc * Bc * NCc * Dc;

    static cudaStream_t s2 = nullptr;
    static cudaEvent_t evFork, evWo, evXat, evMlp, evEmb;
    if (!s2) {
        cudaStreamCreateWithFlags(&s2, cudaStreamNonBlocking);
        cudaEventCreateWithFlags(&evFork, cudaEventDisableTiming);
        cudaEventCreateWithFlags(&evWo,   cudaEventDisableTiming);
        cudaEventCreateWithFlags(&evXat,  cudaEventDisableTiming);
        cudaEventCreateWithFlags(&evMlp,  cudaEventDisableTiming);
        cudaEventCreateWithFlags(&evEmb,  cudaEventDisableTiming);
    }

    __half *wqkv_h, *wqkv_l, *wo_h, *wo_l, *xwq_h, *xwq_l, *xwo_h, *xwo_l;
    __half *w1f, *w2f, *emb_h, *emb_l;
    __half *ck_h, *ck_l, *cv_h, *cv_l;
    float *gx, *pO, *pm, *pl;
    __half *hf, *atf, *hidf, *qf, *kh, *kl, *vh, *vl;
    SYM(wqkv_h, s_Wqkv_h); SYM(wqkv_l, s_Wqkv_l);
    SYM(wo_h, s_Wo_h);  SYM(wo_l, s_Wo_l);
    SYM(xwq_h, s_xWq_h); SYM(xwq_l, s_xWq_l);
    SYM(xwo_h, s_xWo_h); SYM(xwo_l, s_xWo_l);
    SYM(w1f, s_W1f);  SYM(w2f, s_W2f);
    SYM(emb_h, s_emb_h); SYM(emb_l, s_emb_l);
    SYM(ck_h, s_ck_h);  SYM(ck_l, s_ck_l);
    SYM(cv_h, s_cv_h);  SYM(cv_l, s_cv_l);
    SYM(gx, g_x);
    SYM(pO, p_O); SYM(pm, p_m); SYM(pl, p_l);
    SYM(hf, a_hf); SYM(atf, a_atf); SYM(hidf, a_hidf);
    SYM(qf, a_qf);
    SYM(kh, a_k_h); SYM(kl, a_k_l);
    SYM(vh, a_v_h); SYM(vl, a_v_l);

    const long XKV = (long)Bc * CTc * Dc;
    const long LBD = (long)Bc * NCc * Dc;
    const long WQKV = (long)Dc * D3;

    // ---- fork side stream; one-time splits on s2 ----
    cudaEventRecord(evFork, 0);
    cudaStreamWaitEvent(s2, evFork, 0);

    split_fp16(s2, Wo_all,  wo_h,  wo_l,  (long)Lc * DDm);
    cudaEventRecord(evWo, s2);
    split_fp16(s2, xWq_all, xwq_h, xwq_l, (long)Lc * DDm);
    split_fp16(s2, cross_k, ck_h,  ck_l,  (long)Lc * Bc * CTc * Dc);
    split_fp16(s2, cross_v, cv_h,  cv_l,  (long)Lc * Bc * CTc * Dc);
    split_fp16(s2, xWo_all, xwo_h, xwo_l, (long)Lc * DDm);
    cudaEventRecord(evXat, s2);
    cvt_fp16(s2, W1_all,  w1f, (long)Lc * Dc * D4);
    cvt_fp16(s2, W2_all,  w2f, (long)Lc * Dc * D4);
    cudaEventRecord(evMlp, s2);
    split_fp16(s2, tokemb,  emb_h, emb_l, (long)Vc * Dc);
    cudaEventRecord(evEmb, s2);

    // ---- main stream ----
    {
        long n4 = (long)Lc * Dc * 192;
        dim3 grid((unsigned)((n4 + 255) / 256), 3);
        split_qkv3h_kernel<<<grid, 256>>>((const float4*)Wq_all, (const float4*)Wk_all,
                                          (const float4*)Wv_all,
                                          (__half2*)wqkv_h, (__half2*)wqkv_l, n4);
    }
    embed_kernel<<<Mrows, 256>>>(tokens, tokemb, posemb, gx);

    for (int l = 0; l < Lc; l++) {
        float* klayer = kout + l * LBD;
        float* vlayer = vout + l * LBD;

        // ---- self attention ----
        ln_half_kernel<<<Mrows, 256>>>(gx, hf, attn_ln_g + l * Dc, attn_ln_b + l * Dc);
        gemm_qkv_h2<<<dim3(Mrows/64, D3/64), 128>>>(hf,
                                                    wqkv_h + l * WQKV, wqkv_l + l * WQKV,
                                                    bq_all + l * Dc, bv_all + l * Dc,
                                                    qf, kh, kl, vh, vl, klayer, vlayer);
        flash_kernel<1><<<dim3(1, Tc/64, Bc*Hc), 128>>>(qf, kh, kl, vh, vl,
                                                        atf, Tc, Tc);
        if (l == 0) cudaStreamWaitEvent(0, evWo, 0);
        gh_sm<2>(atf, wo_h + (long)l*DDm, wo_l + (long)l*DDm, gx, nullptr,
                 bo_all + l*Dc, Mrows, Dc, Dc, Dc, Dc, Dc, 2);

        // ---- cross attention (split-K flash) ----
        ln_half_kernel<<<Mrows, 256>>>(gx, hf, xln_g + l * Dc, xln_b + l * Dc);
        if (l == 0) cudaStreamWaitEvent(0, evXat, 0);
        gh_sm<2>(hf, xwq_h + (long)l*DDm, xwq_l + (long)l*DDm, nullptr, qf,
                 xbq_all + l*Dc, Mrows, Dc, Dc, Dc, Dc, Dc, 1);
        flashp_kernel<<<dim3(XSPL, Tc/64, Bc*Hc), 128>>>(qf,
                                                         ck_h + l*XKV, ck_l + l*XKV,
                                                         cv_h + l*XKV, cv_l + l*XKV,
                                                         pO, pm, pl, CTc);
        flashc_kernel<<<dim3(Tc, Bc*Hc), HD>>>(pO, pm, pl, atf);
        gh_sm<2>(atf, xwo_h + (long)l*DDm, xwo_l + (long)l*DDm, gx, nullptr,
                 xbo_all + l*Dc, Mrows, Dc, Dc, Dc, Dc, Dc, 2);

        // ---- MLP (1-term fp16 weights) ----
        ln_half_kernel<<<Mrows, 256>>>(gx, hf, mln_g + l * Dc, mln_b + l * Dc);
        if (l == 0) cudaStreamWaitEvent(0, evMlp, 0);
        gh<1>(hf, w1f + (long)l*Dc*D4, nullptr, nullptr, hidf,
              b1_all + (long)l*D4, Mrows, D4, Dc, Dc, D4, D4, 3);
        gh_sm<1>(hidf, w2f + (long)l*Dc*D4, nullptr, gx, nullptr,
                 b2_all + l*Dc, Mrows, Dc, D4, D4, Dc, Dc, 2);
    }

    // final LN (fp16) + fp16 2-term logits GEMM
    ln_half_kernel<<<Mrows, 256>>>(gx, hf, ln_g, ln_b);
    cudaStreamWaitEvent(0, evEmb, 0);
    {
        dim3 grid(Mrows / 64, (Vc + 63) / 64);
        gemm_f16_logits<<<grid, 128>>>(hf, emb_h, emb_l, logits,
                                       Mrows, Vc, Dc, Dc, Dc, Vc);
    }

    (void)in_sizes; (void)n_in; (void)out_size;
}